// round 7
// baseline (speedup 1.0000x reference)
#include <cuda_runtime.h>
#include <cuda_bf16.h>
#include <math.h>

// ---------------- problem constants ----------------
#define BB 16
#define T0 512
#define TR 511
#define PP 1024
#define DD 2048
#define G4 8192   // 4*D
#define NL 4
#define NBLK 128

// ---------------- scratch (device globals; no allocation allowed) ----------------
__device__ __align__(16) float g_xg[(size_t)BB * T0 * G4];      // 256 MB
__device__ __align__(16) float g_bufA[(size_t)BB * T0 * PP];    // 32 MB
__device__ __align__(16) float g_bufB[(size_t)BB * T0 * PP];    // 32 MB
__device__ __align__(16) float g_convA[(size_t)BB * T0 * DD];   // 64 MB
__device__ __align__(16) float g_hs[(size_t)BB * T0 * PP];      // 32 MB
__device__ __align__(16) uint2 g_whp_hi[(size_t)1024 * 64 * 32];  // 16 MB Wh fragment hi
__device__ __align__(16) uint2 g_whp_lo[(size_t)1024 * 64 * 32];  // 16 MB Wh fragment lo
__device__ __align__(16) uint2 g_projp_hi[(size_t)128 * 128 * 32]; // 4 MB proj fragment hi
__device__ __align__(16) uint2 g_projp_lo[(size_t)128 * 128 * 32]; // 4 MB proj fragment lo
__device__ __align__(16) uint4 g_hfh[2048];                     // h A-fragments hi
__device__ __align__(16) uint4 g_hfl[2048];                     // h A-fragments lo
__device__ __align__(16) uint4 g_sfh[4096];                     // s A-fragments hi
__device__ __align__(16) uint4 g_sfl[4096];                     // s A-fragments lo
__device__ __align__(16) float g_c[BB * DD];
__device__ __align__(16) float g_h[BB * PP];
__device__ unsigned int g_bar;

// ================= bf16 split helpers =================
__device__ __forceinline__ void bsplit2(float a, float b, unsigned& hi, unsigned& lo) {
    __nv_bfloat162 h2 = __floats2bfloat162_rn(a, b);
    float ra = a - __bfloat162float(h2.x);
    float rb = b - __bfloat162float(h2.y);
    __nv_bfloat162 l2 = __floats2bfloat162_rn(ra, rb);
    hi = *reinterpret_cast<unsigned*>(&h2);
    lo = *reinterpret_cast<unsigned*>(&l2);
}

__device__ __forceinline__ void mma_bf16(float* c, const unsigned* a, const unsigned* b) {
    asm volatile(
        "mma.sync.aligned.m16n8k16.row.col.f32.bf16.bf16.f32 "
        "{%0,%1,%2,%3},{%4,%5,%6,%7},{%8,%9},{%0,%1,%2,%3};"
        : "+f"(c[0]), "+f"(c[1]), "+f"(c[2]), "+f"(c[3])
        : "r"(a[0]), "r"(a[1]), "r"(a[2]), "r"(a[3]), "r"(b[0]), "r"(b[1]));
}

// ================= weight fragment packer (hi/lo split outputs) =================
// W: K x N row-major. Output [ntile][kstep][lane]: hi2 = {b0_hi, b1_hi}, lo2 = {b0_lo, b1_lo}.
__global__ __launch_bounds__(256) void pack_frag(
    const float* __restrict__ W, uint2* __restrict__ out_hi, uint2* __restrict__ out_lo,
    int N, int ksteps)
{
    __shared__ float tile[8][16][8];
    const int wlocal = threadIdx.x >> 5;
    const int lane = threadIdx.x & 31;
    const int wglob = blockIdx.x * 8 + wlocal;
    const int nt = wglob / ksteps;
    const int ks = wglob - nt * ksteps;

    {
        const int r = lane >> 1;
        const int cb = (lane & 1) * 4;
        float4 v = *(const float4*)&W[(size_t)(ks * 16 + r) * N + nt * 8 + cb];
        tile[wlocal][r][cb + 0] = v.x;
        tile[wlocal][r][cb + 1] = v.y;
        tile[wlocal][r][cb + 2] = v.z;
        tile[wlocal][r][cb + 3] = v.w;
    }
    __syncwarp();

    const int g = lane >> 2;
    const int t = lane & 3;
    float v00 = tile[wlocal][2 * t][g];
    float v01 = tile[wlocal][2 * t + 1][g];
    float v10 = tile[wlocal][2 * t + 8][g];
    float v11 = tile[wlocal][2 * t + 9][g];
    unsigned h0, l0, h1, l1;
    bsplit2(v00, v01, h0, l0);
    bsplit2(v10, v11, h1, l1);
    const size_t idx = ((size_t)(nt * ksteps + ks)) * 32 + lane;
    out_hi[idx] = make_uint2(h0, h1);
    out_lo[idx] = make_uint2(l0, l1);
}

// ================= split-bf16 GEMM: C[M,N] = A[M,K]@B[K,N] + bias =================
#define GBM 128
#define GBN 128
#define GBK 16
#define ASTR (GBM + 8)
#define BSTR (GBN + 8)

__global__ __launch_bounds__(256) void gemm_bf16(
    const float* __restrict__ A, const float* __restrict__ Bw,
    const float* __restrict__ bias, float* __restrict__ C,
    int M, int N, int K)
{
    __shared__ float As[GBK][ASTR];
    __shared__ float Bs[GBK][BSTR];

    const int bm = blockIdx.y * GBM;
    const int bn = blockIdx.x * GBN;
    const int tid = threadIdx.x;
    const int lane = tid & 31;
    const int wid = tid >> 5;
    const int wm = (wid >> 2) * 64;
    const int wn = (wid & 3) * 32;
    const int lg = lane >> 2;
    const int lk = lane & 3;

    float acc[4][4][4];
#pragma unroll
    for (int mt = 0; mt < 4; mt++)
#pragma unroll
        for (int nt = 0; nt < 4; nt++)
#pragma unroll
            for (int r = 0; r < 4; r++) acc[mt][nt][r] = 0.0f;

    for (int k0 = 0; k0 < K; k0 += GBK) {
#pragma unroll
        for (int it = 0; it < 2; it++) {
            int f = tid + it * 256;
            int r = f >> 2;
            int kq = (f & 3) * 4;
            float4 v = make_float4(0.f, 0.f, 0.f, 0.f);
            if (bm + r < M) v = *(const float4*)&A[(size_t)(bm + r) * K + k0 + kq];
            As[kq + 0][r] = v.x;
            As[kq + 1][r] = v.y;
            As[kq + 2][r] = v.z;
            As[kq + 3][r] = v.w;
        }
#pragma unroll
        for (int it = 0; it < 2; it++) {
            int f = tid + it * 256;
            int r = f >> 5;
            int nq = (f & 31) * 4;
            float4 v = *(const float4*)&Bw[(size_t)(k0 + r) * N + bn + nq];
            *(float4*)&Bs[r][nq] = v;
        }
        __syncthreads();

        {
            unsigned ah[4][4], al[4][4], bh[4][2], bl[4][2];
#pragma unroll
            for (int mt = 0; mt < 4; mt++) {
                int row = wm + mt * 16 + lg;
                bsplit2(As[2 * lk][row],     As[2 * lk + 1][row],     ah[mt][0], al[mt][0]);
                bsplit2(As[2 * lk][row + 8], As[2 * lk + 1][row + 8], ah[mt][1], al[mt][1]);
                bsplit2(As[8 + 2 * lk][row],     As[9 + 2 * lk][row],     ah[mt][2], al[mt][2]);
                bsplit2(As[8 + 2 * lk][row + 8], As[9 + 2 * lk][row + 8], ah[mt][3], al[mt][3]);
            }
#pragma unroll
            for (int nt = 0; nt < 4; nt++) {
                int col = wn + nt * 8 + lg;
                bsplit2(Bs[2 * lk][col], Bs[2 * lk + 1][col], bh[nt][0], bl[nt][0]);
                bsplit2(Bs[8 + 2 * lk][col], Bs[9 + 2 * lk][col], bh[nt][1], bl[nt][1]);
            }
#pragma unroll
            for (int mt = 0; mt < 4; mt++)
#pragma unroll
                for (int nt = 0; nt < 4; nt++) {
                    mma_bf16(acc[mt][nt], ah[mt], bh[nt]);
                    mma_bf16(acc[mt][nt], ah[mt], bl[nt]);
                    mma_bf16(acc[mt][nt], al[mt], bh[nt]);
                }
        }
        __syncthreads();
    }

#pragma unroll
    for (int mt = 0; mt < 4; mt++) {
#pragma unroll
        for (int nt = 0; nt < 4; nt++) {
            int row0 = bm + wm + mt * 16 + lg;
            int col0 = bn + wn + nt * 8 + lk * 2;
            float b0 = bias[col0], b1 = bias[col0 + 1];
            if (row0 < M) {
                float2 v = make_float2(acc[mt][nt][0] + b0, acc[mt][nt][1] + b1);
                *(float2*)&C[(size_t)row0 * N + col0] = v;
            }
            if (row0 + 8 < M) {
                float2 v = make_float2(acc[mt][nt][2] + b0, acc[mt][nt][3] + b1);
                *(float2*)&C[(size_t)(row0 + 8) * N + col0] = v;
            }
        }
    }
}

// ================= persistent LSTM layer kernel =================
__device__ __forceinline__ void grid_barrier(unsigned target) {
    __syncthreads();
    __threadfence();
    if (threadIdx.x == 0) {
        atomicAdd(&g_bar, 1u);
        while (*(volatile unsigned int*)&g_bar < target) {
            __nanosleep(20);
        }
    }
    __syncthreads();
}

// smem: Wh-hi slice 128 KB + h-frag hi 32 KB + h-frag lo 32 KB + red/gbuf 8 KB = 200 KB
#define SMEM_BYTES (200 * 1024)

__global__ __launch_bounds__(512, 1) void lstm_persist(
    const float* __restrict__ xg,        // (B*T, 8192)
    const uint2* __restrict__ whp_hi,    // [1024][64][32]
    const uint2* __restrict__ whp_lo,
    const uint2* __restrict__ projp_hi,  // [128][128][32]
    const uint2* __restrict__ projp_lo,
    float* __restrict__ c,               // (16, 2048)
    float* __restrict__ h,               // (16, 1024) scalar (for tail)
    float* __restrict__ hs,              // (B*T, 1024)
    int T)
{
    extern __shared__ __align__(16) char dynsmem[];
    uint2* wh_sm = (uint2*)dynsmem;                    // 16384 uint2 (128 KB)
    uint4* sh_hi = (uint4*)(dynsmem + 131072);         // 2048 uint4 (32 KB)
    uint4* sh_lo = sh_hi + 2048;                       // 2048 uint4 (32 KB)
    float* red   = (float*)(dynsmem + 196608);         // 2048 floats (8 KB)
    float* gbuf  = red + 1024;

    unsigned* sfh32 = (unsigned*)g_sfh;
    unsigned* sfl32 = (unsigned*)g_sfl;
    unsigned* hfh32 = (unsigned*)g_hfh;
    unsigned* hfl32 = (unsigned*)g_hfl;

    const int tid  = threadIdx.x;
    const int lane = tid & 31;
    const int warp = tid >> 5;        // 0..15
    const int bid  = blockIdx.x;
    const int d0   = bid * 16;
    const int p0   = bid * 8;

    // phase A warp mapping
    const int subA = warp & 7;
    const int khA  = warp >> 3;
    const int gateA = subA >> 1;
    const int halfA = subA & 1;
    const int ntA  = gateA * 256 + bid * 2 + halfA;
    const size_t whbase = ((size_t)(ntA * 64 + khA * 32)) * 32 + lane;
    const uint2* wpAlo = whp_lo + whbase;

    const int lg = lane >> 2;
    const int lt = lane & 3;

    // cell-update mapping
    const int cb = tid >> 3;
    const int cj = tid & 7;
    const int s_idx = (((bid * 32) + (cb & 7) * 4 + (cj & 3)) << 2) + ((cb >> 3) + 2 * ((cj >> 2) & 1));
    const int hb = tid >> 3;
    const int hp = tid & 7;
    const int h_idx = ((((bid >> 1) * 32) + (hb & 7) * 4 + (hp >> 1)) << 2) + ((hb >> 3) + 2 * (bid & 1));

    // ---- preload this block's Wh-hi slice into smem (once per layer) ----
    {
        const uint2* src = whp_hi + whbase;
        uint2* dst = wh_sm + (warp * 32) * 32 + lane;
#pragma unroll
        for (int ks = 0; ks < 32; ks++)
            dst[ks * 32] = src[(size_t)ks * 32];
    }
    __syncthreads();
    const uint2* wsm = wh_sm + (warp * 32) * 32 + lane;

    unsigned epoch = 0;

    for (int t = 0; t < T; t++) {
        // ---- prefetch xg + old c ----
        float2 xgv[4], cold;
        if (tid < 128) {
            const size_t xrow = ((size_t)(cb * T + t)) * G4;
            const int dloc = d0 + 2 * cj;
#pragma unroll
            for (int g = 0; g < 4; g++)
                xgv[g] = *(const float2*)&xg[xrow + g * DD + dloc];
            cold = *(const float2*)&c[cb * DD + dloc];
        }

        // ---- stage h A-fragments global -> smem ----
#pragma unroll
        for (int i = 0; i < 4; i++) {
            const int idx = tid + i * 512;
            sh_hi[idx] = __ldcg(&g_hfh[idx]);
            sh_lo[idx] = __ldcg(&g_hfl[idx]);
        }
        __syncthreads();

        // ---- phase A mma: gates = h @ Wh slice (W-hi from smem, W-lo from L2) ----
        float acc[4] = {0.f, 0.f, 0.f, 0.f};
        {
            const uint4* aph = sh_hi + (khA * 32) * 32 + lane;
            const uint4* apl = sh_lo + (khA * 32) * 32 + lane;
#pragma unroll 4
            for (int ks = 0; ks < 32; ks++) {
                uint2 bh2 = wsm[ks * 32];
                uint2 bl2 = __ldcg(&wpAlo[(size_t)ks * 32]);
                uint4 ah = aph[ks * 32];
                uint4 al = apl[ks * 32];
                unsigned bh[2] = {bh2.x, bh2.y};
                unsigned bl[2] = {bl2.x, bl2.y};
                mma_bf16(acc, &ah.x, bh);
                mma_bf16(acc, &ah.x, bl);
                mma_bf16(acc, &al.x, bh);
            }
        }

        // ---- reduce the two k-halves ----
        if (khA == 1) {
#pragma unroll
            for (int r = 0; r < 4; r++) red[(subA * 32 + lane) * 4 + r] = acc[r];
        }
        __syncthreads();
        if (khA == 0) {
#pragma unroll
            for (int r = 0; r < 4; r++) acc[r] += red[(subA * 32 + lane) * 4 + r];
            const int ddb = halfA * 8 + 2 * lt;
            gbuf[(lg * 16 + ddb) * 4 + gateA]           = acc[0];
            gbuf[(lg * 16 + ddb + 1) * 4 + gateA]       = acc[1];
            gbuf[((lg + 8) * 16 + ddb) * 4 + gateA]     = acc[2];
            gbuf[((lg + 8) * 16 + ddb + 1) * 4 + gateA] = acc[3];
        }
        __syncthreads();

        // ---- cell update: writes c (scalar) and s (fragment-native) ----
        if (tid < 128) {
            float4 gv0 = *(float4*)&gbuf[(cb * 16 + 2 * cj) * 4];
            float4 gv1 = *(float4*)&gbuf[(cb * 16 + 2 * cj + 1) * 4];
            float si0 = 1.0f / (1.0f + expf(-(gv0.x + xgv[0].x)));
            float sj0 = tanhf(gv0.y + xgv[1].x);
            float sf0 = 1.0f / (1.0f + expf(-(gv0.z + xgv[2].x + 1.0f)));
            float so0 = 1.0f / (1.0f + expf(-(gv0.w + xgv[3].x)));
            float cn0 = sf0 * cold.x + si0 * sj0;
            float s0 = so0 * tanhf(cn0);
            float si1 = 1.0f / (1.0f + expf(-(gv1.x + xgv[0].y)));
            float sj1 = tanhf(gv1.y + xgv[1].y);
            float sf1 = 1.0f / (1.0f + expf(-(gv1.z + xgv[2].y + 1.0f)));
            float so1 = 1.0f / (1.0f + expf(-(gv1.w + xgv[3].y)));
            float cn1 = sf1 * cold.y + si1 * sj1;
            float s1 = so1 * tanhf(cn1);

            *(float2*)&c[cb * DD + d0 + 2 * cj] = make_float2(cn0, cn1);

            unsigned hiw, low;
            bsplit2(s0, s1, hiw, low);
            sfh32[s_idx] = hiw;
            sfl32[s_idx] = low;
        }

        epoch++;
        grid_barrier(epoch * NBLK);

        // ---- phase B mma: h = s @ proj ----
        float accp[4] = {0.f, 0.f, 0.f, 0.f};
        {
            const size_t pbase = ((size_t)(bid * 128 + warp * 8)) * 32 + lane;
            const uint2* pph = projp_hi + pbase;
            const uint2* ppl = projp_lo + pbase;
            const uint4* aph = g_sfh + (warp * 8) * 32 + lane;
            const uint4* apl = g_sfl + (warp * 8) * 32 + lane;
#pragma unroll
            for (int ks = 0; ks < 8; ks++) {
                uint2 bh2 = __ldcg(&pph[(size_t)ks * 32]);
                uint2 bl2 = __ldcg(&ppl[(size_t)ks * 32]);
                uint4 ah = __ldcg(&aph[ks * 32]);
                uint4 al = __ldcg(&apl[ks * 32]);
                unsigned bh[2] = {bh2.x, bh2.y};
                unsigned bl[2] = {bl2.x, bl2.y};
                mma_bf16(accp, &ah.x, bh);
                mma_bf16(accp, &ah.x, bl);
                mma_bf16(accp, &al.x, bh);
            }
        }
#pragma unroll
        for (int r = 0; r < 4; r++) red[(warp * 32 + lane) * 4 + r] = accp[r];
        __syncthreads();

        if (tid < 128) {
            const int b = hb;
            const int p = hp;
            const int rl = (b & 7) * 4 + (p >> 1);
            const int rr = (b < 8) ? (p & 1) : (2 + (p & 1));
            float v = 0.0f;
#pragma unroll
            for (int w = 0; w < 16; w++) v += red[(w * 32 + rl) * 4 + rr];
            h[b * PP + p0 + p] = v;
            hs[((size_t)(b * T + t)) * PP + p0 + p] = v;
            float vp = __shfl_xor_sync(0xffffffffu, v, 1);
            if ((tid & 1) == 0) {
                unsigned hiw, low;
                bsplit2(v, vp, hiw, low);
                hfh32[h_idx] = hiw;
                hfl32[h_idx] = low;
            }
        }

        epoch++;
        grid_barrier(epoch * NBLK);
    }
}

// ================= pack initial h into fragment form =================
__global__ __launch_bounds__(256) void pack_h_init(const float* __restrict__ h)
{
    unsigned* hfh32 = (unsigned*)g_hfh;
    unsigned* hfl32 = (unsigned*)g_hfl;
    int idx = blockIdx.x * 256 + threadIdx.x;
    if (idx >= BB * 512) return;
    int b = idx >> 9;
    int j = idx & 511;
    float v0 = h[b * PP + 2 * j];
    float v1 = h[b * PP + 2 * j + 1];
    int ks = j >> 3;
    int khalf = (j >> 2) & 1;
    int tq = j & 3;
    int lane = (b & 7) * 4 + tq;
    int comp = (b >> 3) + 2 * khalf;
    unsigned hiw, low;
    bsplit2(v0, v1, hiw, low);
    hfh32[((ks * 32 + lane) << 2) + comp] = hiw;
    hfl32[((ks * 32 + lane) << 2) + comp] = low;
}

// ================= LayerNorm over rows of 1024 =================
__global__ __launch_bounds__(256) void ln_kernel(
    const float* __restrict__ x, const float* __restrict__ gam,
    const float* __restrict__ bet, float* __restrict__ y)
{
    __shared__ float sred[256];
    const size_t r = blockIdx.x;
    const float* xr = x + r * PP;
    const int tid = threadIdx.x;

    float v[4];
#pragma unroll
    for (int i = 0; i < 4; i++) v[i] = xr[tid + i * 256];
    float sm = v[0] + v[1] + v[2] + v[3];
    sred[tid] = sm;
    __syncthreads();
    for (int off = 128; off > 0; off >>= 1) {
        if (tid < off) sred[tid] += sred[tid + off];
        __syncthreads();
    }
    float mean = sred[0] * (1.0f / 1024.0f);
    __syncthreads();

    float q = 0.0f;
#pragma unroll
    for (int i = 0; i < 4; i++) { float d = v[i] - mean; q += d * d; }
    sred[tid] = q;
    __syncthreads();
    for (int off = 128; off > 0; off >>= 1) {
        if (tid < off) sred[tid] += sred[tid + off];
        __syncthreads();
    }
    float inv = rsqrtf(sred[0] * (1.0f / 1024.0f) + 1e-3f);

#pragma unroll
    for (int i = 0; i < 4; i++) {
        int col = tid + i * 256;
        y[r * PP + col] = (v[i] - mean) * inv * gam[col] + bet[col];
    }
}

// ================= conv im2col =================
__global__ __launch_bounds__(256) void build_convA(
    const float* __restrict__ ln, float* __restrict__ Acat)
{
    size_t idx = (size_t)blockIdx.x * 256 + threadIdx.x;
    if (idx >= (size_t)BB * TR * DD) return;
    int m = (int)(idx >> 11);
    int k = (int)(idx & 2047);
    int b = m / TR;
    int t = m - b * TR;
    int w = k >> 10;
    int p = k & 1023;
    Acat[idx] = ln[((size_t)(b * T0 + t + w)) * PP + p];
}

// ================= init / reset / tail =================
__global__ __launch_bounds__(256) void init_state(
    const float* __restrict__ state, float* __restrict__ c, float* __restrict__ h)
{
    int i = blockIdx.x * 256 + threadIdx.x;
    if (i < BB * DD) c[i] = state[i];
    if (i < BB * PP) {
        int b = i >> 10, p = i & 1023;
        h[i] = state[BB * DD + b * DD + p];
    }
}

__global__ void reset_bar() { g_bar = 0u; }

__global__ __launch_bounds__(256) void write_tail(
    const float* __restrict__ c, const float* __restrict__ h, float* __restrict__ out)
{
    const size_t base = (size_t)BB * TR * PP;
    int i = blockIdx.x * 256 + threadIdx.x;
    if (i < BB * DD) out[base + i] = c[i];
    if (i < BB * PP) out[base + BB * DD + i] = h[i];
}

// ================= orchestration =================
extern "C" void kernel_launch(void* const* d_in, const int* in_sizes, int n_in,
                              void* d_out, int out_size)
{
    const float* inputs  = (const float*)d_in[0];
    const float* state   = (const float*)d_in[1];
    const float* kernels = (const float*)d_in[2];
    const float* biases  = (const float*)d_in[3];
    const float* projs   = (const float*)d_in[4];
    const float* gamma   = (const float*)d_in[5];
    const float* beta    = (const float*)d_in[6];
    const float* convw   = (const float*)d_in[7];
    const float* convb   = (const float*)d_in[8];
    float* out = (float*)d_out;

    float *xg, *bufA, *bufB, *convA, *hs, *c, *h;
    uint2 *whph, *whpl, *prph, *prpl;
    cudaGetSymbolAddress((void**)&xg,    g_xg);
    cudaGetSymbolAddress((void**)&bufA,  g_bufA);
    cudaGetSymbolAddress((void**)&bufB,  g_bufB);
    cudaGetSymbolAddress((void**)&convA, g_convA);
    cudaGetSymbolAddress((void**)&hs,    g_hs);
    cudaGetSymbolAddress((void**)&whph,  g_whp_hi);
    cudaGetSymbolAddress((void**)&whpl,  g_whp_lo);
    cudaGetSymbolAddress((void**)&prph,  g_projp_hi);
    cudaGetSymbolAddress((void**)&prpl,  g_projp_lo);
    cudaGetSymbolAddress((void**)&c,     g_c);
    cudaGetSymbolAddress((void**)&h,     g_h);

    static int smem_set = 0;
    if (!smem_set) {
        cudaFuncSetAttribute(lstm_persist, cudaFuncAttributeMaxDynamicSharedMemorySize, SMEM_BYTES);
        smem_set = 1;
    }

    init_state<<<128, 256>>>(state, c, h);
    pack_h_init<<<32, 256>>>(h);

    const float* x = inputs;
    int T = T0;
    for (int l = 0; l < NL; l++) {
        const float* Wx = kernels + (size_t)l * 2 * PP * G4;
        const float* Wh = Wx + (size_t)PP * G4;
        const float* bi = biases + (size_t)l * G4;
        const float* pr = projs + (size_t)l * DD * PP;
        const int M = BB * T;

        pack_frag<<<(1024 * 64) / 8, 256>>>(Wh, whph, whpl, G4, 64);
        pack_frag<<<(128 * 128) / 8, 256>>>(pr, prph, prpl, PP, 128);

        dim3 g1(G4 / GBN, (M + GBM - 1) / GBM);
        gemm_bf16<<<g1, 256>>>(x, Wx, bi, xg, M, G4, PP);

        reset_bar<<<1, 1>>>();
        lstm_persist<<<NBLK, 512, SMEM_BYTES>>>(xg, whph, whpl, prph, prpl, c, h, hs, T);

        float* lnout = (l == 0) ? bufA : (l == 1) ? bufB : (l == 2) ? bufA : out;
        ln_kernel<<<BB * T, 256>>>(hs, gamma, beta, lnout);

        if (l == 1) {
            build_convA<<<(BB * TR * DD + 255) / 256, 256>>>(bufB, convA);
            dim3 g2(PP / GBN, (BB * TR + GBM - 1) / GBM);
            gemm_bf16<<<g2, 256>>>(convA, convw, convb, bufA, BB * TR, PP, DD);
            T = TR;
            x = bufA;
        } else {
            x = bufA;
        }
    }

    write_tail<<<128, 256>>>(c, h, out);
}

// round 8
// speedup vs baseline: 1.0519x; 1.0519x over previous
#include <cuda_runtime.h>
#include <cuda_bf16.h>
#include <math.h>

// ---------------- problem constants ----------------
#define BB 16
#define T0 512
#define TR 511
#define PP 1024
#define DD 2048
#define G4 8192   // 4*D
#define NL 4
#define NBLK 128

// ---------------- scratch (device globals; no allocation allowed) ----------------
__device__ __align__(16) float g_xg[(size_t)BB * T0 * G4];      // 256 MB
__device__ __align__(16) float g_bufA[(size_t)BB * T0 * PP];    // 32 MB
__device__ __align__(16) float g_bufB[(size_t)BB * T0 * PP];    // 32 MB
__device__ __align__(16) float g_convA[(size_t)BB * T0 * DD];   // 64 MB
__device__ __align__(16) float g_hs[(size_t)BB * T0 * PP];      // 32 MB
__device__ __align__(16) uint4 g_whp[(size_t)1024 * 64 * 32];   // 32 MB packed Wh fragments
__device__ __align__(16) uint4 g_projp[(size_t)128 * 128 * 32]; // 8 MB packed proj fragments
__device__ __align__(16) uint4 g_hfh[2048];                     // h A-fragments hi
__device__ __align__(16) uint4 g_hfl[2048];                     // h A-fragments lo
__device__ __align__(16) uint4 g_sfh[4096];                     // s A-fragments hi
__device__ __align__(16) uint4 g_sfl[4096];                     // s A-fragments lo
__device__ __align__(16) float g_c[BB * DD];
__device__ __align__(16) float g_h[BB * PP];
// 8 distributed barrier counters, each on its own 128-byte line
__device__ __align__(128) unsigned int g_bar8[8 * 32];

// ================= bf16 split helpers =================
__device__ __forceinline__ void bsplit2(float a, float b, unsigned& hi, unsigned& lo) {
    __nv_bfloat162 h2 = __floats2bfloat162_rn(a, b);
    float ra = a - __bfloat162float(h2.x);
    float rb = b - __bfloat162float(h2.y);
    __nv_bfloat162 l2 = __floats2bfloat162_rn(ra, rb);
    hi = *reinterpret_cast<unsigned*>(&h2);
    lo = *reinterpret_cast<unsigned*>(&l2);
}

__device__ __forceinline__ void mma_bf16(float* c, const unsigned* a, const unsigned* b) {
    asm volatile(
        "mma.sync.aligned.m16n8k16.row.col.f32.bf16.bf16.f32 "
        "{%0,%1,%2,%3},{%4,%5,%6,%7},{%8,%9},{%0,%1,%2,%3};"
        : "+f"(c[0]), "+f"(c[1]), "+f"(c[2]), "+f"(c[3])
        : "r"(a[0]), "r"(a[1]), "r"(a[2]), "r"(a[3]), "r"(b[0]), "r"(b[1]));
}

// ================= weight fragment packer =================
// W: K x N row-major. Output: [ntile][kstep][lane] uint4 {b0_hi,b1_hi,b0_lo,b1_lo}.
__global__ __launch_bounds__(256) void pack_frag(
    const float* __restrict__ W, uint4* __restrict__ out, int N, int ksteps)
{
    __shared__ float tile[8][16][8];
    const int wlocal = threadIdx.x >> 5;
    const int lane = threadIdx.x & 31;
    const int wglob = blockIdx.x * 8 + wlocal;
    const int nt = wglob / ksteps;
    const int ks = wglob - nt * ksteps;

    {
        const int r = lane >> 1;
        const int cb = (lane & 1) * 4;
        float4 v = *(const float4*)&W[(size_t)(ks * 16 + r) * N + nt * 8 + cb];
        tile[wlocal][r][cb + 0] = v.x;
        tile[wlocal][r][cb + 1] = v.y;
        tile[wlocal][r][cb + 2] = v.z;
        tile[wlocal][r][cb + 3] = v.w;
    }
    __syncwarp();

    const int g = lane >> 2;
    const int t = lane & 3;
    float v00 = tile[wlocal][2 * t][g];
    float v01 = tile[wlocal][2 * t + 1][g];
    float v10 = tile[wlocal][2 * t + 8][g];
    float v11 = tile[wlocal][2 * t + 9][g];
    uint4 o;
    bsplit2(v00, v01, o.x, o.z);
    bsplit2(v10, v11, o.y, o.w);
    out[((size_t)(nt * ksteps + ks)) * 32 + lane] = o;
}

// ================= split-bf16 GEMM: C[M,N] = A[M,K]@B[K,N] + bias =================
#define GBM 128
#define GBN 128
#define GBK 16
#define ASTR (GBM + 8)
#define BSTR (GBN + 8)

__global__ __launch_bounds__(256) void gemm_bf16(
    const float* __restrict__ A, const float* __restrict__ Bw,
    const float* __restrict__ bias, float* __restrict__ C,
    int M, int N, int K)
{
    // fold barrier reset into the GEMM that precedes each lstm_persist launch
    if (blockIdx.x == 0 && blockIdx.y == 0 && threadIdx.x < 8)
        g_bar8[threadIdx.x * 32] = 0u;

    __shared__ float As[GBK][ASTR];
    __shared__ float Bs[GBK][BSTR];

    const int bm = blockIdx.y * GBM;
    const int bn = blockIdx.x * GBN;
    const int tid = threadIdx.x;
    const int lane = tid & 31;
    const int wid = tid >> 5;
    const int wm = (wid >> 2) * 64;
    const int wn = (wid & 3) * 32;
    const int lg = lane >> 2;
    const int lk = lane & 3;

    float acc[4][4][4];
#pragma unroll
    for (int mt = 0; mt < 4; mt++)
#pragma unroll
        for (int nt = 0; nt < 4; nt++)
#pragma unroll
            for (int r = 0; r < 4; r++) acc[mt][nt][r] = 0.0f;

    for (int k0 = 0; k0 < K; k0 += GBK) {
#pragma unroll
        for (int it = 0; it < 2; it++) {
            int f = tid + it * 256;
            int r = f >> 2;
            int kq = (f & 3) * 4;
            float4 v = make_float4(0.f, 0.f, 0.f, 0.f);
            if (bm + r < M) v = *(const float4*)&A[(size_t)(bm + r) * K + k0 + kq];
            As[kq + 0][r] = v.x;
            As[kq + 1][r] = v.y;
            As[kq + 2][r] = v.z;
            As[kq + 3][r] = v.w;
        }
#pragma unroll
        for (int it = 0; it < 2; it++) {
            int f = tid + it * 256;
            int r = f >> 5;
            int nq = (f & 31) * 4;
            float4 v = *(const float4*)&Bw[(size_t)(k0 + r) * N + bn + nq];
            *(float4*)&Bs[r][nq] = v;
        }
        __syncthreads();

        {
            unsigned ah[4][4], al[4][4], bh[4][2], bl[4][2];
#pragma unroll
            for (int mt = 0; mt < 4; mt++) {
                int row = wm + mt * 16 + lg;
                bsplit2(As[2 * lk][row],     As[2 * lk + 1][row],     ah[mt][0], al[mt][0]);
                bsplit2(As[2 * lk][row + 8], As[2 * lk + 1][row + 8], ah[mt][1], al[mt][1]);
                bsplit2(As[8 + 2 * lk][row],     As[9 + 2 * lk][row],     ah[mt][2], al[mt][2]);
                bsplit2(As[8 + 2 * lk][row + 8], As[9 + 2 * lk][row + 8], ah[mt][3], al[mt][3]);
            }
#pragma unroll
            for (int nt = 0; nt < 4; nt++) {
                int col = wn + nt * 8 + lg;
                bsplit2(Bs[2 * lk][col], Bs[2 * lk + 1][col], bh[nt][0], bl[nt][0]);
                bsplit2(Bs[8 + 2 * lk][col], Bs[9 + 2 * lk][col], bh[nt][1], bl[nt][1]);
            }
#pragma unroll
            for (int mt = 0; mt < 4; mt++)
#pragma unroll
                for (int nt = 0; nt < 4; nt++) {
                    mma_bf16(acc[mt][nt], ah[mt], bh[nt]);
                    mma_bf16(acc[mt][nt], ah[mt], bl[nt]);
                    mma_bf16(acc[mt][nt], al[mt], bh[nt]);
                }
        }
        __syncthreads();
    }

#pragma unroll
    for (int mt = 0; mt < 4; mt++) {
#pragma unroll
        for (int nt = 0; nt < 4; nt++) {
            int row0 = bm + wm + mt * 16 + lg;
            int col0 = bn + wn + nt * 8 + lk * 2;
            float b0 = bias[col0], b1 = bias[col0 + 1];
            if (row0 < M) {
                float2 v = make_float2(acc[mt][nt][0] + b0, acc[mt][nt][1] + b1);
                *(float2*)&C[(size_t)row0 * N + col0] = v;
            }
            if (row0 + 8 < M) {
                float2 v = make_float2(acc[mt][nt][2] + b0, acc[mt][nt][3] + b1);
                *(float2*)&C[(size_t)(row0 + 8) * N + col0] = v;
            }
        }
    }
}

// ================= persistent LSTM layer kernel (tensor-core, frag-native state) =================
// Distributed barrier: 8 counters, block bid&7 -> counter; 16 arrivals per counter per epoch.
__device__ __forceinline__ void grid_barrier(unsigned target16, int bid) {
    __syncthreads();
    __threadfence();
    if (threadIdx.x == 0)
        atomicAdd(&g_bar8[(bid & 7) * 32], 1u);
    if (threadIdx.x < 8) {
        while (__ldcg(&g_bar8[threadIdx.x * 32]) < target16) {
            __nanosleep(20);
        }
    }
    __syncthreads();
}

// smem: h-frag hi 32KB + h-frag lo 32KB + red/gbuf 8KB = 72KB
#define SMEM_BYTES (72 * 1024)

__global__ __launch_bounds__(512, 1) void lstm_persist(
    const float* __restrict__ xg,       // (B*T, 8192)
    const uint4* __restrict__ whp,      // packed Wh fragments [1024][64][32]
    const uint4* __restrict__ projp,    // packed proj fragments [128][128][32]
    float* __restrict__ c,              // (16, 2048)
    float* __restrict__ h,              // (16, 1024) scalar (for tail)
    float* __restrict__ hs,             // (B*T, 1024)
    int T)
{
    extern __shared__ __align__(16) char dynsmem[];
    uint4* sh_hi = (uint4*)dynsmem;                 // 2048 uint4
    uint4* sh_lo = sh_hi + 2048;                    // 2048 uint4
    float* red   = (float*)(dynsmem + 64 * 1024);   // 2048 floats
    float* gbuf  = red + 1024;

    unsigned* sfh32 = (unsigned*)g_sfh;
    unsigned* sfl32 = (unsigned*)g_sfl;
    unsigned* hfh32 = (unsigned*)g_hfh;
    unsigned* hfl32 = (unsigned*)g_hfl;

    const int tid  = threadIdx.x;
    const int lane = tid & 31;
    const int warp = tid >> 5;        // 0..15
    const int bid  = blockIdx.x;
    const int d0   = bid * 16;
    const int p0   = bid * 8;

    // phase A warp mapping
    const int subA = warp & 7;
    const int khA  = warp >> 3;       // k-half of 1024
    const int gateA = subA >> 1;
    const int halfA = subA & 1;
    const int ntA  = gateA * 256 + bid * 2 + halfA;
    const uint4* wpA = whp + ((size_t)(ntA * 64 + khA * 32)) * 32 + lane;

    const int lg = lane >> 2;
    const int lt = lane & 3;

    // cell-update mapping (tid < 128)
    const int cb = tid >> 3;
    const int cj = tid & 7;
    const int s_idx = (((bid * 32) + (cb & 7) * 4 + (cj & 3)) << 2) + ((cb >> 3) + 2 * ((cj >> 2) & 1));
    const int hb = tid >> 3;
    const int hp = tid & 7;
    const int h_idx = ((((bid >> 1) * 32) + (hb & 7) * 4 + (hp >> 1)) << 2) + ((hb >> 3) + 2 * (bid & 1));

    unsigned epoch = 0;

    for (int t = 0; t < T; t++) {
        // ---- prefetch xg (4 gates x d-pair) + old c ----
        float2 xgv[4], cold;
        if (tid < 128) {
            const size_t xrow = ((size_t)(cb * T + t)) * G4;
            const int dloc = d0 + 2 * cj;
#pragma unroll
            for (int g = 0; g < 4; g++)
                xgv[g] = *(const float2*)&xg[xrow + g * DD + dloc];
            cold = *(const float2*)&c[cb * DD + dloc];
        }

        // ---- stage h A-fragments global -> smem ----
#pragma unroll
        for (int i = 0; i < 4; i++) {
            const int idx = tid + i * 512;
            sh_hi[idx] = __ldcg(&g_hfh[idx]);
            sh_lo[idx] = __ldcg(&g_hfl[idx]);
        }
        __syncthreads();

        // ---- phase A mma: gates = h @ Wh slice ----
        float acc[4] = {0.f, 0.f, 0.f, 0.f};
        {
            const uint4* aph = sh_hi + (khA * 32) * 32 + lane;
            const uint4* apl = sh_lo + (khA * 32) * 32 + lane;
#pragma unroll 4
            for (int ks = 0; ks < 32; ks++) {
                uint4 bfrag = wpA[(size_t)ks * 32];
                uint4 ah = aph[ks * 32];
                uint4 al = apl[ks * 32];
                unsigned bh[2] = {bfrag.x, bfrag.y};
                unsigned bl[2] = {bfrag.z, bfrag.w};
                mma_bf16(acc, &ah.x, bh);
                mma_bf16(acc, &ah.x, bl);
                mma_bf16(acc, &al.x, bh);
            }
        }

        // ---- reduce the two k-halves ----
        if (khA == 1) {
#pragma unroll
            for (int r = 0; r < 4; r++) red[(subA * 32 + lane) * 4 + r] = acc[r];
        }
        __syncthreads();
        if (khA == 0) {
#pragma unroll
            for (int r = 0; r < 4; r++) acc[r] += red[(subA * 32 + lane) * 4 + r];
            const int ddb = halfA * 8 + 2 * lt;
            gbuf[(lg * 16 + ddb) * 4 + gateA]           = acc[0];
            gbuf[(lg * 16 + ddb + 1) * 4 + gateA]       = acc[1];
            gbuf[((lg + 8) * 16 + ddb) * 4 + gateA]     = acc[2];
            gbuf[((lg + 8) * 16 + ddb + 1) * 4 + gateA] = acc[3];
        }
        __syncthreads();

        // ---- cell update: writes c (scalar) and s (fragment-native) ----
        if (tid < 128) {
            float4 gv0 = *(float4*)&gbuf[(cb * 16 + 2 * cj) * 4];
            float4 gv1 = *(float4*)&gbuf[(cb * 16 + 2 * cj + 1) * 4];
            float si0 = 1.0f / (1.0f + expf(-(gv0.x + xgv[0].x)));
            float sj0 = tanhf(gv0.y + xgv[1].x);
            float sf0 = 1.0f / (1.0f + expf(-(gv0.z + xgv[2].x + 1.0f)));
            float so0 = 1.0f / (1.0f + expf(-(gv0.w + xgv[3].x)));
            float cn0 = sf0 * cold.x + si0 * sj0;
            float s0 = so0 * tanhf(cn0);
            float si1 = 1.0f / (1.0f + expf(-(gv1.x + xgv[0].y)));
            float sj1 = tanhf(gv1.y + xgv[1].y);
            float sf1 = 1.0f / (1.0f + expf(-(gv1.z + xgv[2].y + 1.0f)));
            float so1 = 1.0f / (1.0f + expf(-(gv1.w + xgv[3].y)));
            float cn1 = sf1 * cold.y + si1 * sj1;
            float s1 = so1 * tanhf(cn1);

            *(float2*)&c[cb * DD + d0 + 2 * cj] = make_float2(cn0, cn1);

            unsigned hiw, low;
            bsplit2(s0, s1, hiw, low);
            sfh32[s_idx] = hiw;
            sfl32[s_idx] = low;
        }

        epoch++;
        grid_barrier(epoch * 16, bid);

        // ---- phase B mma: h = s @ proj (warp w covers ksteps [8w, 8w+8), frags from L2) ----
        float accp[4] = {0.f, 0.f, 0.f, 0.f};
        {
            const uint4* pp = projp + ((size_t)(bid * 128 + warp * 8)) * 32 + lane;
            const uint4* aph = g_sfh + (warp * 8) * 32 + lane;
            const uint4* apl = g_sfl + (warp * 8) * 32 + lane;
#pragma unroll
            for (int ks = 0; ks < 8; ks++) {
                uint4 bfrag = pp[(size_t)ks * 32];
                uint4 ah = __ldcg(&aph[ks * 32]);
                uint4 al = __ldcg(&apl[ks * 32]);
                unsigned bh[2] = {bfrag.x, bfrag.y};
                unsigned bl[2] = {bfrag.z, bfrag.w};
                mma_bf16(accp, &ah.x, bh);
                mma_bf16(accp, &ah.x, bl);
                mma_bf16(accp, &al.x, bh);
            }
        }
#pragma unroll
        for (int r = 0; r < 4; r++) red[(warp * 32 + lane) * 4 + r] = accp[r];
        __syncthreads();

        if (tid < 128) {
            const int b = hb;
            const int p = hp;
            const int rl = (b & 7) * 4 + (p >> 1);
            const int rr = (b < 8) ? (p & 1) : (2 + (p & 1));
            float v = 0.0f;
#pragma unroll
            for (int w = 0; w < 16; w++) v += red[(w * 32 + rl) * 4 + rr];
            h[b * PP + p0 + p] = v;
            hs[((size_t)(b * T + t)) * PP + p0 + p] = v;
            float vp = __shfl_xor_sync(0xffffffffu, v, 1);
            if ((tid & 1) == 0) {
                unsigned hiw, low;
                bsplit2(v, vp, hiw, low);
                hfh32[h_idx] = hiw;
                hfl32[h_idx] = low;
            }
        }

        epoch++;
        grid_barrier(epoch * 16, bid);
    }
}

// ================= pack initial h into fragment form =================
__global__ __launch_bounds__(256) void pack_h_init(const float* __restrict__ h)
{
    unsigned* hfh32 = (unsigned*)g_hfh;
    unsigned* hfl32 = (unsigned*)g_hfl;
    int idx = blockIdx.x * 256 + threadIdx.x;
    if (idx >= BB * 512) return;
    int b = idx >> 9;
    int j = idx & 511;
    float v0 = h[b * PP + 2 * j];
    float v1 = h[b * PP + 2 * j + 1];
    int ks = j >> 3;
    int khalf = (j >> 2) & 1;
    int tq = j & 3;
    int lane = (b & 7) * 4 + tq;
    int comp = (b >> 3) + 2 * khalf;
    unsigned hiw, low;
    bsplit2(v0, v1, hiw, low);
    hfh32[((ks * 32 + lane) << 2) + comp] = hiw;
    hfl32[((ks * 32 + lane) << 2) + comp] = low;
}

// ================= LayerNorm over rows of 1024 =================
__global__ __launch_bounds__(256) void ln_kernel(
    const float* __restrict__ x, const float* __restrict__ gam,
    const float* __restrict__ bet, float* __restrict__ y)
{
    __shared__ float sred[256];
    const size_t r = blockIdx.x;
    const float* xr = x + r * PP;
    const int tid = threadIdx.x;

    float v[4];
#pragma unroll
    for (int i = 0; i < 4; i++) v[i] = xr[tid + i * 256];
    float sm = v[0] + v[1] + v[2] + v[3];
    sred[tid] = sm;
    __syncthreads();
    for (int off = 128; off > 0; off >>= 1) {
        if (tid < off) sred[tid] += sred[tid + off];
        __syncthreads();
    }
    float mean = sred[0] * (1.0f / 1024.0f);
    __syncthreads();

    float q = 0.0f;
#pragma unroll
    for (int i = 0; i < 4; i++) { float d = v[i] - mean; q += d * d; }
    sred[tid] = q;
    __syncthreads();
    for (int off = 128; off > 0; off >>= 1) {
        if (tid < off) sred[tid] += sred[tid + off];
        __syncthreads();
    }
    float inv = rsqrtf(sred[0] * (1.0f / 1024.0f) + 1e-3f);

#pragma unroll
    for (int i = 0; i < 4; i++) {
        int col = tid + i * 256;
        y[r * PP + col] = (v[i] - mean) * inv * gam[col] + bet[col];
    }
}

// ================= conv im2col =================
__global__ __launch_bounds__(256) void build_convA(
    const float* __restrict__ ln, float* __restrict__ Acat)
{
    size_t idx = (size_t)blockIdx.x * 256 + threadIdx.x;
    if (idx >= (size_t)BB * TR * DD) return;
    int m = (int)(idx >> 11);
    int k = (int)(idx & 2047);
    int b = m / TR;
    int t = m - b * TR;
    int w = k >> 10;
    int p = k & 1023;
    Acat[idx] = ln[((size_t)(b * T0 + t + w)) * PP + p];
}

// ================= init / tail =================
__global__ __launch_bounds__(256) void init_state(
    const float* __restrict__ state, float* __restrict__ c, float* __restrict__ h)
{
    int i = blockIdx.x * 256 + threadIdx.x;
    if (i < BB * DD) c[i] = state[i];
    if (i < BB * PP) {
        int b = i >> 10, p = i & 1023;
        h[i] = state[BB * DD + b * DD + p];
    }
}

__global__ __launch_bounds__(256) void write_tail(
    const float* __restrict__ c, const float* __restrict__ h, float* __restrict__ out)
{
    const size_t base = (size_t)BB * TR * PP;
    int i = blockIdx.x * 256 + threadIdx.x;
    if (i < BB * DD) out[base + i] = c[i];
    if (i < BB * PP) out[base + BB * DD + i] = h[i];
}

// ================= orchestration =================
extern "C" void kernel_launch(void* const* d_in, const int* in_sizes, int n_in,
                              void* d_out, int out_size)
{
    const float* inputs  = (const float*)d_in[0];
    const float* state   = (const float*)d_in[1];
    const float* kernels = (const float*)d_in[2];
    const float* biases  = (const float*)d_in[3];
    const float* projs   = (const float*)d_in[4];
    const float* gamma   = (const float*)d_in[5];
    const float* beta    = (const float*)d_in[6];
    const float* convw   = (const float*)d_in[7];
    const float* convb   = (const float*)d_in[8];
    float* out = (float*)d_out;

    float *xg, *bufA, *bufB, *convA, *hs, *c, *h;
    uint4 *whp, *projp;
    cudaGetSymbolAddress((void**)&xg,    g_xg);
    cudaGetSymbolAddress((void**)&bufA,  g_bufA);
    cudaGetSymbolAddress((void**)&bufB,  g_bufB);
    cudaGetSymbolAddress((void**)&convA, g_convA);
    cudaGetSymbolAddress((void**)&hs,    g_hs);
    cudaGetSymbolAddress((void**)&whp,   g_whp);
    cudaGetSymbolAddress((void**)&projp, g_projp);
    cudaGetSymbolAddress((void**)&c,     g_c);
    cudaGetSymbolAddress((void**)&h,     g_h);

    static int smem_set = 0;
    if (!smem_set) {
        cudaFuncSetAttribute(lstm_persist, cudaFuncAttributeMaxDynamicSharedMemorySize, SMEM_BYTES);
        smem_set = 1;
    }

    init_state<<<128, 256>>>(state, c, h);
    pack_h_init<<<32, 256>>>(h);

    const float* x = inputs;
    int T = T0;
    for (int l = 0; l < NL; l++) {
        const float* Wx = kernels + (size_t)l * 2 * PP * G4;
        const float* Wh = Wx + (size_t)PP * G4;
        const float* bi = biases + (size_t)l * G4;
        const float* pr = projs + (size_t)l * DD * PP;
        const int M = BB * T;

        pack_frag<<<(1024 * 64) / 8, 256>>>(Wh, whp, G4, 64);
        pack_frag<<<(128 * 128) / 8, 256>>>(pr, projp, PP, 128);

        dim3 g1(G4 / GBN, (M + GBM - 1) / GBM);
        gemm_bf16<<<g1, 256>>>(x, Wx, bi, xg, M, G4, PP);   // also resets barrier counters

        lstm_persist<<<NBLK, 512, SMEM_BYTES>>>(xg, whp, projp, c, h, hs, T);

        float* lnout = (l == 0) ? bufA : (l == 1) ? bufB : (l == 2) ? bufA : out;
        ln_kernel<<<BB * T, 256>>>(hs, gamma, beta, lnout);

        if (l == 1) {
            build_convA<<<(BB * TR * DD + 255) / 256, 256>>>(bufB, convA);
            dim3 g2(PP / GBN, (BB * TR + GBM - 1) / GBM);
            gemm_bf16<<<g2, 256>>>(convA, convw, convb, bufA, BB * TR, PP, DD);
            T = TR;
            x = bufA;
        } else {
            x = bufA;
        }
    }

    write_tail<<<128, 256>>>(c, h, out);
}

// round 9
// speedup vs baseline: 1.0616x; 1.0092x over previous
#include <cuda_runtime.h>
#include <cuda_bf16.h>
#include <math.h>

// ---------------- problem constants ----------------
#define BB 16
#define T0 512
#define TR 511
#define PP 1024
#define DD 2048
#define G4 8192   // 4*D
#define NL 4
#define NBLK 128

// ---------------- scratch (device globals; no allocation allowed) ----------------
__device__ __align__(16) float g_xg[(size_t)BB * T0 * G4];      // 256 MB
__device__ __align__(16) float g_bufA[(size_t)BB * T0 * PP];    // 32 MB
__device__ __align__(16) float g_bufB[(size_t)BB * T0 * PP];    // 32 MB
__device__ __align__(16) float g_convA[(size_t)BB * T0 * DD];   // 64 MB
__device__ __align__(16) float g_hs[(size_t)BB * T0 * PP];      // 32 MB
__device__ __align__(16) uint4 g_whp[(size_t)1024 * 64 * 32];   // 32 MB packed Wh fragments
__device__ __align__(16) uint4 g_projp[(size_t)128 * 128 * 32]; // 8 MB packed proj fragments
__device__ __align__(16) uint4 g_hfh[2048];                     // h A-fragments hi
__device__ __align__(16) uint4 g_hfl[2048];                     // h A-fragments lo
__device__ __align__(16) uint4 g_sfh[4096];                     // s A-fragments hi
__device__ __align__(16) uint4 g_sfl[4096];                     // s A-fragments lo
__device__ __align__(16) float g_c[BB * DD];
__device__ __align__(16) float g_h[BB * PP];
// 8 distributed barrier counters, each on its own 128-byte line
__device__ __align__(128) unsigned int g_bar8[8 * 32];

// ================= bf16 split helpers =================
__device__ __forceinline__ void bsplit2(float a, float b, unsigned& hi, unsigned& lo) {
    __nv_bfloat162 h2 = __floats2bfloat162_rn(a, b);
    float ra = a - __bfloat162float(h2.x);
    float rb = b - __bfloat162float(h2.y);
    __nv_bfloat162 l2 = __floats2bfloat162_rn(ra, rb);
    hi = *reinterpret_cast<unsigned*>(&h2);
    lo = *reinterpret_cast<unsigned*>(&l2);
}

__device__ __forceinline__ void mma_bf16(float* c, const unsigned* a, const unsigned* b) {
    asm volatile(
        "mma.sync.aligned.m16n8k16.row.col.f32.bf16.bf16.f32 "
        "{%0,%1,%2,%3},{%4,%5,%6,%7},{%8,%9},{%0,%1,%2,%3};"
        : "+f"(c[0]), "+f"(c[1]), "+f"(c[2]), "+f"(c[3])
        : "r"(a[0]), "r"(a[1]), "r"(a[2]), "r"(a[3]), "r"(b[0]), "r"(b[1]));
}

// 3-term split mma: hi*hi + hi*lo + lo*hi into one accumulator
__device__ __forceinline__ void mma3(float* acc, const uint4& ah, const uint4& al, const uint4& bf) {
    unsigned bh[2] = {bf.x, bf.y};
    unsigned bl[2] = {bf.z, bf.w};
    mma_bf16(acc, &ah.x, bh);
    mma_bf16(acc, &ah.x, bl);
    mma_bf16(acc, &al.x, bh);
}

// ================= weight fragment packer =================
// W: K x N row-major. Output: [ntile][kstep][lane] uint4 {b0_hi,b1_hi,b0_lo,b1_lo}.
__global__ __launch_bounds__(256) void pack_frag(
    const float* __restrict__ W, uint4* __restrict__ out, int N, int ksteps)
{
    __shared__ float tile[8][16][8];
    const int wlocal = threadIdx.x >> 5;
    const int lane = threadIdx.x & 31;
    const int wglob = blockIdx.x * 8 + wlocal;
    const int nt = wglob / ksteps;
    const int ks = wglob - nt * ksteps;

    {
        const int r = lane >> 1;
        const int cb = (lane & 1) * 4;
        float4 v = *(const float4*)&W[(size_t)(ks * 16 + r) * N + nt * 8 + cb];
        tile[wlocal][r][cb + 0] = v.x;
        tile[wlocal][r][cb + 1] = v.y;
        tile[wlocal][r][cb + 2] = v.z;
        tile[wlocal][r][cb + 3] = v.w;
    }
    __syncwarp();

    const int g = lane >> 2;
    const int t = lane & 3;
    float v00 = tile[wlocal][2 * t][g];
    float v01 = tile[wlocal][2 * t + 1][g];
    float v10 = tile[wlocal][2 * t + 8][g];
    float v11 = tile[wlocal][2 * t + 9][g];
    uint4 o;
    bsplit2(v00, v01, o.x, o.z);
    bsplit2(v10, v11, o.y, o.w);
    out[((size_t)(nt * ksteps + ks)) * 32 + lane] = o;
}

// ================= split-bf16 GEMM: C[M,N] = A[M,K]@B[K,N] + bias =================
#define GBM 128
#define GBN 128
#define GBK 16
#define ASTR (GBM + 8)
#define BSTR (GBN + 8)

__global__ __launch_bounds__(256) void gemm_bf16(
    const float* __restrict__ A, const float* __restrict__ Bw,
    const float* __restrict__ bias, float* __restrict__ C,
    int M, int N, int K)
{
    // fold barrier reset into the GEMM that precedes each lstm_persist launch
    if (blockIdx.x == 0 && blockIdx.y == 0 && threadIdx.x < 8)
        g_bar8[threadIdx.x * 32] = 0u;

    __shared__ float As[GBK][ASTR];
    __shared__ float Bs[GBK][BSTR];

    const int bm = blockIdx.y * GBM;
    const int bn = blockIdx.x * GBN;
    const int tid = threadIdx.x;
    const int lane = tid & 31;
    const int wid = tid >> 5;
    const int wm = (wid >> 2) * 64;
    const int wn = (wid & 3) * 32;
    const int lg = lane >> 2;
    const int lk = lane & 3;

    float acc[4][4][4];
#pragma unroll
    for (int mt = 0; mt < 4; mt++)
#pragma unroll
        for (int nt = 0; nt < 4; nt++)
#pragma unroll
            for (int r = 0; r < 4; r++) acc[mt][nt][r] = 0.0f;

    for (int k0 = 0; k0 < K; k0 += GBK) {
#pragma unroll
        for (int it = 0; it < 2; it++) {
            int f = tid + it * 256;
            int r = f >> 2;
            int kq = (f & 3) * 4;
            float4 v = make_float4(0.f, 0.f, 0.f, 0.f);
            if (bm + r < M) v = *(const float4*)&A[(size_t)(bm + r) * K + k0 + kq];
            As[kq + 0][r] = v.x;
            As[kq + 1][r] = v.y;
            As[kq + 2][r] = v.z;
            As[kq + 3][r] = v.w;
        }
#pragma unroll
        for (int it = 0; it < 2; it++) {
            int f = tid + it * 256;
            int r = f >> 5;
            int nq = (f & 31) * 4;
            float4 v = *(const float4*)&Bw[(size_t)(k0 + r) * N + bn + nq];
            *(float4*)&Bs[r][nq] = v;
        }
        __syncthreads();

        {
            unsigned ah[4][4], al[4][4], bh[4][2], bl[4][2];
#pragma unroll
            for (int mt = 0; mt < 4; mt++) {
                int row = wm + mt * 16 + lg;
                bsplit2(As[2 * lk][row],     As[2 * lk + 1][row],     ah[mt][0], al[mt][0]);
                bsplit2(As[2 * lk][row + 8], As[2 * lk + 1][row + 8], ah[mt][1], al[mt][1]);
                bsplit2(As[8 + 2 * lk][row],     As[9 + 2 * lk][row],     ah[mt][2], al[mt][2]);
                bsplit2(As[8 + 2 * lk][row + 8], As[9 + 2 * lk][row + 8], ah[mt][3], al[mt][3]);
            }
#pragma unroll
            for (int nt = 0; nt < 4; nt++) {
                int col = wn + nt * 8 + lg;
                bsplit2(Bs[2 * lk][col], Bs[2 * lk + 1][col], bh[nt][0], bl[nt][0]);
                bsplit2(Bs[8 + 2 * lk][col], Bs[9 + 2 * lk][col], bh[nt][1], bl[nt][1]);
            }
#pragma unroll
            for (int mt = 0; mt < 4; mt++)
#pragma unroll
                for (int nt = 0; nt < 4; nt++) {
                    mma_bf16(acc[mt][nt], ah[mt], bh[nt]);
                    mma_bf16(acc[mt][nt], ah[mt], bl[nt]);
                    mma_bf16(acc[mt][nt], al[mt], bh[nt]);
                }
        }
        __syncthreads();
    }

#pragma unroll
    for (int mt = 0; mt < 4; mt++) {
#pragma unroll
        for (int nt = 0; nt < 4; nt++) {
            int row0 = bm + wm + mt * 16 + lg;
            int col0 = bn + wn + nt * 8 + lk * 2;
            float b0 = bias[col0], b1 = bias[col0 + 1];
            if (row0 < M) {
                float2 v = make_float2(acc[mt][nt][0] + b0, acc[mt][nt][1] + b1);
                *(float2*)&C[(size_t)row0 * N + col0] = v;
            }
            if (row0 + 8 < M) {
                float2 v = make_float2(acc[mt][nt][2] + b0, acc[mt][nt][3] + b1);
                *(float2*)&C[(size_t)(row0 + 8) * N + col0] = v;
            }
        }
    }
}

// ================= persistent LSTM layer kernel (tensor-core, frag-native state) =================
// Distributed barrier with release/acquire atomics (no __threadfence -> no CCTL.IVALL L1 flush).
// All cross-block data is read via __ldcg (L2), so L1 coherence is not needed.
__device__ __forceinline__ void grid_barrier(unsigned target16, int bid) {
    __syncthreads();
    if (threadIdx.x == 0) {
        asm volatile("red.release.gpu.global.add.u32 [%0], 1;"
                     :: "l"(&g_bar8[(bid & 7) * 32]) : "memory");
    }
    if (threadIdx.x < 8) {
        unsigned v;
        while (true) {
            asm volatile("ld.acquire.gpu.global.u32 %0, [%1];"
                         : "=r"(v) : "l"(&g_bar8[threadIdx.x * 32]) : "memory");
            if (v >= target16) break;
            __nanosleep(20);
        }
    }
    __syncthreads();
}

// smem: h-frag hi 32KB + h-frag lo 32KB + red/gbuf 8KB = 72KB
#define SMEM_BYTES (72 * 1024)

__global__ __launch_bounds__(512, 1) void lstm_persist(
    const float* __restrict__ xg,       // (B*T, 8192)
    const uint4* __restrict__ whp,      // packed Wh fragments [1024][64][32]
    const uint4* __restrict__ projp,    // packed proj fragments [128][128][32]
    float* __restrict__ c,              // (16, 2048)
    float* __restrict__ h,              // (16, 1024) scalar (for tail)
    float* __restrict__ hs,             // (B*T, 1024)
    int T)
{
    extern __shared__ __align__(16) char dynsmem[];
    uint4* sh_hi = (uint4*)dynsmem;                 // 2048 uint4
    uint4* sh_lo = sh_hi + 2048;                    // 2048 uint4
    float* red   = (float*)(dynsmem + 64 * 1024);   // 2048 floats
    float* gbuf  = red + 1024;

    unsigned* sfh32 = (unsigned*)g_sfh;
    unsigned* sfl32 = (unsigned*)g_sfl;
    unsigned* hfh32 = (unsigned*)g_hfh;
    unsigned* hfl32 = (unsigned*)g_hfl;

    const int tid  = threadIdx.x;
    const int lane = tid & 31;
    const int warp = tid >> 5;        // 0..15
    const int bid  = blockIdx.x;
    const int d0   = bid * 16;
    const int p0   = bid * 8;

    // phase A warp mapping
    const int subA = warp & 7;
    const int khA  = warp >> 3;       // k-half of 1024
    const int gateA = subA >> 1;
    const int halfA = subA & 1;
    const int ntA  = gateA * 256 + bid * 2 + halfA;
    const uint4* wpA = whp + ((size_t)(ntA * 64 + khA * 32)) * 32 + lane;

    const int lg = lane >> 2;
    const int lt = lane & 3;

    // cell-update mapping (tid < 128)
    const int cb = tid >> 3;
    const int cj = tid & 7;
    const int s_idx = (((bid * 32) + (cb & 7) * 4 + (cj & 3)) << 2) + ((cb >> 3) + 2 * ((cj >> 2) & 1));
    const int hb = tid >> 3;
    const int hp = tid & 7;
    const int h_idx = ((((bid >> 1) * 32) + (hb & 7) * 4 + (hp >> 1)) << 2) + ((hb >> 3) + 2 * (bid & 1));

    unsigned epoch = 0;

    for (int t = 0; t < T; t++) {
        // ---- prefetch xg (4 gates x d-pair) + old c ----
        float2 xgv[4], cold;
        if (tid < 128) {
            const size_t xrow = ((size_t)(cb * T + t)) * G4;
            const int dloc = d0 + 2 * cj;
#pragma unroll
            for (int g = 0; g < 4; g++)
                xgv[g] = *(const float2*)&xg[xrow + g * DD + dloc];
            cold = *(const float2*)&c[cb * DD + dloc];
        }

        // ---- stage h A-fragments global -> smem ----
#pragma unroll
        for (int i = 0; i < 4; i++) {
            const int idx = tid + i * 512;
            sh_hi[idx] = __ldcg(&g_hfh[idx]);
            sh_lo[idx] = __ldcg(&g_hfl[idx]);
        }
        __syncthreads();

        // ---- phase A mma: gates = h @ Wh slice (4 independent accumulators) ----
        float a0[4] = {0.f, 0.f, 0.f, 0.f};
        float a1[4] = {0.f, 0.f, 0.f, 0.f};
        float a2[4] = {0.f, 0.f, 0.f, 0.f};
        float a3[4] = {0.f, 0.f, 0.f, 0.f};
        {
            const uint4* aph = sh_hi + (khA * 32) * 32 + lane;
            const uint4* apl = sh_lo + (khA * 32) * 32 + lane;
#pragma unroll 2
            for (int ks = 0; ks < 32; ks += 4) {
                uint4 b0 = wpA[(size_t)(ks + 0) * 32];
                uint4 b1 = wpA[(size_t)(ks + 1) * 32];
                uint4 b2 = wpA[(size_t)(ks + 2) * 32];
                uint4 b3 = wpA[(size_t)(ks + 3) * 32];
                uint4 ah0 = aph[(ks + 0) * 32], al0 = apl[(ks + 0) * 32];
                uint4 ah1 = aph[(ks + 1) * 32], al1 = apl[(ks + 1) * 32];
                uint4 ah2 = aph[(ks + 2) * 32], al2 = apl[(ks + 2) * 32];
                uint4 ah3 = aph[(ks + 3) * 32], al3 = apl[(ks + 3) * 32];
                mma3(a0, ah0, al0, b0);
                mma3(a1, ah1, al1, b1);
                mma3(a2, ah2, al2, b2);
                mma3(a3, ah3, al3, b3);
            }
        }
        float acc[4];
#pragma unroll
        for (int r = 0; r < 4; r++) acc[r] = (a0[r] + a1[r]) + (a2[r] + a3[r]);

        // ---- reduce the two k-halves ----
        if (khA == 1) {
#pragma unroll
            for (int r = 0; r < 4; r++) red[(subA * 32 + lane) * 4 + r] = acc[r];
        }
        __syncthreads();
        if (khA == 0) {
#pragma unroll
            for (int r = 0; r < 4; r++) acc[r] += red[(subA * 32 + lane) * 4 + r];
            const int ddb = halfA * 8 + 2 * lt;
            gbuf[(lg * 16 + ddb) * 4 + gateA]           = acc[0];
            gbuf[(lg * 16 + ddb + 1) * 4 + gateA]       = acc[1];
            gbuf[((lg + 8) * 16 + ddb) * 4 + gateA]     = acc[2];
            gbuf[((lg + 8) * 16 + ddb + 1) * 4 + gateA] = acc[3];
        }
        __syncthreads();

        // ---- cell update: writes c (scalar) and s (fragment-native) ----
        if (tid < 128) {
            float4 gv0 = *(float4*)&gbuf[(cb * 16 + 2 * cj) * 4];
            float4 gv1 = *(float4*)&gbuf[(cb * 16 + 2 * cj + 1) * 4];
            float si0 = 1.0f / (1.0f + expf(-(gv0.x + xgv[0].x)));
            float sj0 = tanhf(gv0.y + xgv[1].x);
            float sf0 = 1.0f / (1.0f + expf(-(gv0.z + xgv[2].x + 1.0f)));
            float so0 = 1.0f / (1.0f + expf(-(gv0.w + xgv[3].x)));
            float cn0 = sf0 * cold.x + si0 * sj0;
            float s0 = so0 * tanhf(cn0);
            float si1 = 1.0f / (1.0f + expf(-(gv1.x + xgv[0].y)));
            float sj1 = tanhf(gv1.y + xgv[1].y);
            float sf1 = 1.0f / (1.0f + expf(-(gv1.z + xgv[2].y + 1.0f)));
            float so1 = 1.0f / (1.0f + expf(-(gv1.w + xgv[3].y)));
            float cn1 = sf1 * cold.y + si1 * sj1;
            float s1 = so1 * tanhf(cn1);

            *(float2*)&c[cb * DD + d0 + 2 * cj] = make_float2(cn0, cn1);

            unsigned hiw, low;
            bsplit2(s0, s1, hiw, low);
            sfh32[s_idx] = hiw;
            sfl32[s_idx] = low;
        }

        epoch++;
        grid_barrier(epoch * 16, bid);

        // ---- phase B mma: h = s @ proj (2 independent accumulators, frags from L2) ----
        float p0a[4] = {0.f, 0.f, 0.f, 0.f};
        float p1a[4] = {0.f, 0.f, 0.f, 0.f};
        {
            const uint4* pp = projp + ((size_t)(bid * 128 + warp * 8)) * 32 + lane;
            const uint4* aph = g_sfh + (warp * 8) * 32 + lane;
            const uint4* apl = g_sfl + (warp * 8) * 32 + lane;
#pragma unroll
            for (int ks = 0; ks < 8; ks += 2) {
                uint4 b0 = pp[(size_t)(ks + 0) * 32];
                uint4 b1 = pp[(size_t)(ks + 1) * 32];
                uint4 ah0 = __ldcg(&aph[(ks + 0) * 32]);
                uint4 al0 = __ldcg(&apl[(ks + 0) * 32]);
                uint4 ah1 = __ldcg(&aph[(ks + 1) * 32]);
                uint4 al1 = __ldcg(&apl[(ks + 1) * 32]);
                mma3(p0a, ah0, al0, b0);
                mma3(p1a, ah1, al1, b1);
            }
        }
        float accp[4];
#pragma unroll
        for (int r = 0; r < 4; r++) accp[r] = p0a[r] + p1a[r];

#pragma unroll
        for (int r = 0; r < 4; r++) red[(warp * 32 + lane) * 4 + r] = accp[r];
        __syncthreads();

        if (tid < 128) {
            const int b = hb;
            const int p = hp;
            const int rl = (b & 7) * 4 + (p >> 1);
            const int rr = (b < 8) ? (p & 1) : (2 + (p & 1));
            float v = 0.0f;
#pragma unroll
            for (int w = 0; w < 16; w++) v += red[(w * 32 + rl) * 4 + rr];
            h[b * PP + p0 + p] = v;
            hs[((size_t)(b * T + t)) * PP + p0 + p] = v;
            float vp = __shfl_xor_sync(0xffffffffu, v, 1);
            if ((tid & 1) == 0) {
                unsigned hiw, low;
                bsplit2(v, vp, hiw, low);
                hfh32[h_idx] = hiw;
                hfl32[h_idx] = low;
            }
        }

        epoch++;
        grid_barrier(epoch * 16, bid);
    }
}

// ================= pack initial h into fragment form =================
__global__ __launch_bounds__(256) void pack_h_init(const float* __restrict__ h)
{
    unsigned* hfh32 = (unsigned*)g_hfh;
    unsigned* hfl32 = (unsigned*)g_hfl;
    int idx = blockIdx.x * 256 + threadIdx.x;
    if (idx >= BB * 512) return;
    int b = idx >> 9;
    int j = idx & 511;
    float v0 = h[b * PP + 2 * j];
    float v1 = h[b * PP + 2 * j + 1];
    int ks = j >> 3;
    int khalf = (j >> 2) & 1;
    int tq = j & 3;
    int lane = (b & 7) * 4 + tq;
    int comp = (b >> 3) + 2 * khalf;
    unsigned hiw, low;
    bsplit2(v0, v1, hiw, low);
    hfh32[((ks * 32 + lane) << 2) + comp] = hiw;
    hfl32[((ks * 32 + lane) << 2) + comp] = low;
}

// ================= LayerNorm over rows of 1024 =================
__global__ __launch_bounds__(256) void ln_kernel(
    const float* __restrict__ x, const float* __restrict__ gam,
    const float* __restrict__ bet, float* __restrict__ y)
{
    __shared__ float sred[256];
    const size_t r = blockIdx.x;
    const float* xr = x + r * PP;
    const int tid = threadIdx.x;

    float v[4];
#pragma unroll
    for (int i = 0; i < 4; i++) v[i] = xr[tid + i * 256];
    float sm = v[0] + v[1] + v[2] + v[3];
    sred[tid] = sm;
    __syncthreads();
    for (int off = 128; off > 0; off >>= 1) {
        if (tid < off) sred[tid] += sred[tid + off];
        __syncthreads();
    }
    float mean = sred[0] * (1.0f / 1024.0f);
    __syncthreads();

    float q = 0.0f;
#pragma unroll
    for (int i = 0; i < 4; i++) { float d = v[i] - mean; q += d * d; }
    sred[tid] = q;
    __syncthreads();
    for (int off = 128; off > 0; off >>= 1) {
        if (tid < off) sred[tid] += sred[tid + off];
        __syncthreads();
    }
    float inv = rsqrtf(sred[0] * (1.0f / 1024.0f) + 1e-3f);

#pragma unroll
    for (int i = 0; i < 4; i++) {
        int col = tid + i * 256;
        y[r * PP + col] = (v[i] - mean) * inv * gam[col] + bet[col];
    }
}

// ================= conv im2col =================
__global__ __launch_bounds__(256) void build_convA(
    const float* __restrict__ ln, float* __restrict__ Acat)
{
    size_t idx = (size_t)blockIdx.x * 256 + threadIdx.x;
    if (idx >= (size_t)BB * TR * DD) return;
    int m = (int)(idx >> 11);
    int k = (int)(idx & 2047);
    int b = m / TR;
    int t = m - b * TR;
    int w = k >> 10;
    int p = k & 1023;
    Acat[idx] = ln[((size_t)(b * T0 + t + w)) * PP + p];
}

// ================= init / tail =================
__global__ __launch_bounds__(256) void init_state(
    const float* __restrict__ state, float* __restrict__ c, float* __restrict__ h)
{
    int i = blockIdx.x * 256 + threadIdx.x;
    if (i < BB * DD) c[i] = state[i];
    if (i < BB * PP) {
        int b = i >> 10, p = i & 1023;
        h[i] = state[BB * DD + b * DD + p];
    }
}

__global__ __launch_bounds__(256) void write_tail(
    const float* __restrict__ c, const float* __restrict__ h, float* __restrict__ out)
{
    const size_t base = (size_t)BB * TR * PP;
    int i = blockIdx.x * 256 + threadIdx.x;
    if (i < BB * DD) out[base + i] = c[i];
    if (i < BB * PP) out[base + BB * DD + i] = h[i];
}

// ================= orchestration =================
extern "C" void kernel_launch(void* const* d_in, const int* in_sizes, int n_in,
                              void* d_out, int out_size)
{
    const float* inputs  = (const float*)d_in[0];
    const float* state   = (const float*)d_in[1];
    const float* kernels = (const float*)d_in[2];
    const float* biases  = (const float*)d_in[3];
    const float* projs   = (const float*)d_in[4];
    const float* gamma   = (const float*)d_in[5];
    const float* beta    = (const float*)d_in[6];
    const float* convw   = (const float*)d_in[7];
    const float* convb   = (const float*)d_in[8];
    float* out = (float*)d_out;

    float *xg, *bufA, *bufB, *convA, *hs, *c, *h;
    uint4 *whp, *projp;
    cudaGetSymbolAddress((void**)&xg,    g_xg);
    cudaGetSymbolAddress((void**)&bufA,  g_bufA);
    cudaGetSymbolAddress((void**)&bufB,  g_bufB);
    cudaGetSymbolAddress((void**)&convA, g_convA);
    cudaGetSymbolAddress((void**)&hs,    g_hs);
    cudaGetSymbolAddress((void**)&whp,   g_whp);
    cudaGetSymbolAddress((void**)&projp, g_projp);
    cudaGetSymbolAddress((void**)&c,     g_c);
    cudaGetSymbolAddress((void**)&h,     g_h);

    static int smem_set = 0;
    if (!smem_set) {
        cudaFuncSetAttribute(lstm_persist, cudaFuncAttributeMaxDynamicSharedMemorySize, SMEM_BYTES);
        smem_set = 1;
    }

    init_state<<<128, 256>>>(state, c, h);
    pack_h_init<<<32, 256>>>(h);

    const float* x = inputs;
    int T = T0;
    for (int l = 0; l < NL; l++) {
        const float* Wx = kernels + (size_t)l * 2 * PP * G4;
        const float* Wh = Wx + (size_t)PP * G4;
        const float* bi = biases + (size_t)l * G4;
        const float* pr = projs + (size_t)l * DD * PP;
        const int M = BB * T;

        pack_frag<<<(1024 * 64) / 8, 256>>>(Wh, whp, G4, 64);
        pack_frag<<<(128 * 128) / 8, 256>>>(pr, projp, PP, 128);

        dim3 g1(G4 / GBN, (M + GBM - 1) / GBM);
        gemm_bf16<<<g1, 256>>>(x, Wx, bi, xg, M, G4, PP);   // also resets barrier counters

        lstm_persist<<<NBLK, 512, SMEM_BYTES>>>(xg, whp, projp, c, h, hs, T);

        float* lnout = (l == 0) ? bufA : (l == 1) ? bufB : (l == 2) ? bufA : out;
        ln_kernel<<<BB * T, 256>>>(hs, gamma, beta, lnout);

        if (l == 1) {
            build_convA<<<(BB * TR * DD + 255) / 256, 256>>>(bufB, convA);
            dim3 g2(PP / GBN, (BB * TR + GBM - 1) / GBM);
            gemm_bf16<<<g2, 256>>>(convA, convw, convb, bufA, BB * TR, PP, DD);
            T = TR;
            x = bufA;
        } else {
            x = bufA;
        }
    }

    write_tail<<<128, 256>>>(c, h, out);
}

// round 10
// speedup vs baseline: 1.0708x; 1.0087x over previous
#include <cuda_runtime.h>
#include <cuda_bf16.h>
#include <math.h>

// ---------------- problem constants ----------------
#define BB 16
#define T0 512
#define TR 511
#define PP 1024
#define DD 2048
#define G4 8192   // 4*D
#define NL 4
#define NBLK 128

// ---------------- scratch (device globals; no allocation allowed) ----------------
__device__ __align__(16) float g_xg[(size_t)BB * T0 * G4];      // 256 MB
__device__ __align__(16) float g_bufA[(size_t)BB * T0 * PP];    // 32 MB
__device__ __align__(16) float g_bufB[(size_t)BB * T0 * PP];    // 32 MB
__device__ __align__(16) float g_convA[(size_t)BB * T0 * DD];   // 64 MB
__device__ __align__(16) float g_hs[(size_t)BB * T0 * PP];      // 32 MB
__device__ __align__(16) uint4 g_whp[(size_t)1024 * 64 * 32];   // 32 MB packed Wh fragments
__device__ __align__(16) uint4 g_projp[(size_t)128 * 128 * 32]; // 8 MB packed proj fragments
__device__ __align__(16) uint4 g_hfh[2048];                     // h A-fragments hi
__device__ __align__(16) uint4 g_hfl[2048];                     // h A-fragments lo
__device__ __align__(16) uint4 g_sfh[4096];                     // s A-fragments hi
__device__ __align__(16) uint4 g_sfl[4096];                     // s A-fragments lo
__device__ __align__(16) float g_c[BB * DD];
__device__ __align__(16) float g_h[BB * PP];
// 8 distributed barrier counters, each on its own 128-byte line
__device__ __align__(128) unsigned int g_bar8[8 * 32];

// ================= bf16 split helpers =================
__device__ __forceinline__ void bsplit2(float a, float b, unsigned& hi, unsigned& lo) {
    __nv_bfloat162 h2 = __floats2bfloat162_rn(a, b);
    float ra = a - __bfloat162float(h2.x);
    float rb = b - __bfloat162float(h2.y);
    __nv_bfloat162 l2 = __floats2bfloat162_rn(ra, rb);
    hi = *reinterpret_cast<unsigned*>(&h2);
    lo = *reinterpret_cast<unsigned*>(&l2);
}

__device__ __forceinline__ void mma_bf16(float* c, const unsigned* a, const unsigned* b) {
    asm volatile(
        "mma.sync.aligned.m16n8k16.row.col.f32.bf16.bf16.f32 "
        "{%0,%1,%2,%3},{%4,%5,%6,%7},{%8,%9},{%0,%1,%2,%3};"
        : "+f"(c[0]), "+f"(c[1]), "+f"(c[2]), "+f"(c[3])
        : "r"(a[0]), "r"(a[1]), "r"(a[2]), "r"(a[3]), "r"(b[0]), "r"(b[1]));
}

// 3-term split mma: hi*hi + hi*lo + lo*hi into one accumulator
__device__ __forceinline__ void mma3(float* acc, const uint4& ah, const uint4& al, const uint4& bf) {
    unsigned bh[2] = {bf.x, bf.y};
    unsigned bl[2] = {bf.z, bf.w};
    mma_bf16(acc, &ah.x, bh);
    mma_bf16(acc, &ah.x, bl);
    mma_bf16(acc, &al.x, bh);
}

// ================= setup: init c/h + pack initial h fragments =================
__global__ __launch_bounds__(256) void setup_all(const float* __restrict__ state)
{
    unsigned* hfh32 = (unsigned*)g_hfh;
    unsigned* hfl32 = (unsigned*)g_hfl;
    int i = blockIdx.x * 256 + threadIdx.x;   // grid 128 -> 32768 threads
    if (i < BB * DD) g_c[i] = state[i];
    if (i < BB * PP) {
        int b = i >> 10, p = i & 1023;
        g_h[i] = state[BB * DD + b * DD + p];
    }
    if (i < BB * 512) {
        int b = i >> 9;
        int j = i & 511;
        float v0 = state[BB * DD + b * DD + 2 * j];
        float v1 = state[BB * DD + b * DD + 2 * j + 1];
        int ks = j >> 3;
        int khalf = (j >> 2) & 1;
        int tq = j & 3;
        int lane = (b & 7) * 4 + tq;
        int comp = (b >> 3) + 2 * khalf;
        unsigned hiw, low;
        bsplit2(v0, v1, hiw, low);
        hfh32[((ks * 32 + lane) << 2) + comp] = hiw;
        hfl32[((ks * 32 + lane) << 2) + comp] = low;
    }
}

// ================= combined weight fragment packer (Wh + proj in one launch) =================
// Output: [ntile][kstep][lane] uint4 {b0_hi,b1_hi,b0_lo,b1_lo}.
__global__ __launch_bounds__(256) void pack_both(
    const float* __restrict__ Wh, uint4* __restrict__ whp,
    const float* __restrict__ proj, uint4* __restrict__ projp)
{
    const float* W;
    uint4* out;
    int N, ksteps, bx = blockIdx.x;
    if (bx < 8192) { W = Wh; out = whp; N = G4; ksteps = 64; }
    else           { W = proj; out = projp; N = PP; ksteps = 128; bx -= 8192; }

    __shared__ float tile[8][16][8];
    const int wlocal = threadIdx.x >> 5;
    const int lane = threadIdx.x & 31;
    const int wglob = bx * 8 + wlocal;
    const int nt = wglob / ksteps;
    const int ks = wglob - nt * ksteps;

    {
        const int r = lane >> 1;
        const int cb = (lane & 1) * 4;
        float4 v = *(const float4*)&W[(size_t)(ks * 16 + r) * N + nt * 8 + cb];
        tile[wlocal][r][cb + 0] = v.x;
        tile[wlocal][r][cb + 1] = v.y;
        tile[wlocal][r][cb + 2] = v.z;
        tile[wlocal][r][cb + 3] = v.w;
    }
    __syncwarp();

    const int g = lane >> 2;
    const int t = lane & 3;
    float v00 = tile[wlocal][2 * t][g];
    float v01 = tile[wlocal][2 * t + 1][g];
    float v10 = tile[wlocal][2 * t + 8][g];
    float v11 = tile[wlocal][2 * t + 9][g];
    uint4 o;
    bsplit2(v00, v01, o.x, o.z);
    bsplit2(v10, v11, o.y, o.w);
    out[((size_t)(nt * ksteps + ks)) * 32 + lane] = o;
}

// ================= split-bf16 GEMM: C[M,N] = A[M,K]@B[K,N] + bias =================
#define GBM 128
#define GBN 128
#define GBK 16
#define ASTR (GBM + 8)
#define BSTR (GBN + 8)

__global__ __launch_bounds__(256) void gemm_bf16(
    const float* __restrict__ A, const float* __restrict__ Bw,
    const float* __restrict__ bias, float* __restrict__ C,
    int M, int N, int K)
{
    // fold barrier reset into the GEMM that precedes each lstm_persist launch
    if (blockIdx.x == 0 && blockIdx.y == 0 && threadIdx.x < 8)
        g_bar8[threadIdx.x * 32] = 0u;

    __shared__ float As[GBK][ASTR];
    __shared__ float Bs[GBK][BSTR];

    const int bm = blockIdx.y * GBM;
    const int bn = blockIdx.x * GBN;
    const int tid = threadIdx.x;
    const int lane = tid & 31;
    const int wid = tid >> 5;
    const int wm = (wid >> 2) * 64;
    const int wn = (wid & 3) * 32;
    const int lg = lane >> 2;
    const int lk = lane & 3;

    float acc[4][4][4];
#pragma unroll
    for (int mt = 0; mt < 4; mt++)
#pragma unroll
        for (int nt = 0; nt < 4; nt++)
#pragma unroll
            for (int r = 0; r < 4; r++) acc[mt][nt][r] = 0.0f;

    for (int k0 = 0; k0 < K; k0 += GBK) {
#pragma unroll
        for (int it = 0; it < 2; it++) {
            int f = tid + it * 256;
            int r = f >> 2;
            int kq = (f & 3) * 4;
            float4 v = make_float4(0.f, 0.f, 0.f, 0.f);
            if (bm + r < M) v = *(const float4*)&A[(size_t)(bm + r) * K + k0 + kq];
            As[kq + 0][r] = v.x;
            As[kq + 1][r] = v.y;
            As[kq + 2][r] = v.z;
            As[kq + 3][r] = v.w;
        }
#pragma unroll
        for (int it = 0; it < 2; it++) {
            int f = tid + it * 256;
            int r = f >> 5;
            int nq = (f & 31) * 4;
            float4 v = *(const float4*)&Bw[(size_t)(k0 + r) * N + bn + nq];
            *(float4*)&Bs[r][nq] = v;
        }
        __syncthreads();

        {
            unsigned ah[4][4], al[4][4], bh[4][2], bl[4][2];
#pragma unroll
            for (int mt = 0; mt < 4; mt++) {
                int row = wm + mt * 16 + lg;
                bsplit2(As[2 * lk][row],     As[2 * lk + 1][row],     ah[mt][0], al[mt][0]);
                bsplit2(As[2 * lk][row + 8], As[2 * lk + 1][row + 8], ah[mt][1], al[mt][1]);
                bsplit2(As[8 + 2 * lk][row],     As[9 + 2 * lk][row],     ah[mt][2], al[mt][2]);
                bsplit2(As[8 + 2 * lk][row + 8], As[9 + 2 * lk][row + 8], ah[mt][3], al[mt][3]);
            }
#pragma unroll
            for (int nt = 0; nt < 4; nt++) {
                int col = wn + nt * 8 + lg;
                bsplit2(Bs[2 * lk][col], Bs[2 * lk + 1][col], bh[nt][0], bl[nt][0]);
                bsplit2(Bs[8 + 2 * lk][col], Bs[9 + 2 * lk][col], bh[nt][1], bl[nt][1]);
            }
#pragma unroll
            for (int mt = 0; mt < 4; mt++)
#pragma unroll
                for (int nt = 0; nt < 4; nt++) {
                    mma_bf16(acc[mt][nt], ah[mt], bh[nt]);
                    mma_bf16(acc[mt][nt], ah[mt], bl[nt]);
                    mma_bf16(acc[mt][nt], al[mt], bh[nt]);
                }
        }
        __syncthreads();
    }

#pragma unroll
    for (int mt = 0; mt < 4; mt++) {
#pragma unroll
        for (int nt = 0; nt < 4; nt++) {
            int row0 = bm + wm + mt * 16 + lg;
            int col0 = bn + wn + nt * 8 + lk * 2;
            float b0 = bias[col0], b1 = bias[col0 + 1];
            if (row0 < M) {
                float2 v = make_float2(acc[mt][nt][0] + b0, acc[mt][nt][1] + b1);
                *(float2*)&C[(size_t)row0 * N + col0] = v;
            }
            if (row0 + 8 < M) {
                float2 v = make_float2(acc[mt][nt][2] + b0, acc[mt][nt][3] + b1);
                *(float2*)&C[(size_t)(row0 + 8) * N + col0] = v;
            }
        }
    }
}

// ================= persistent LSTM layer kernel (tensor-core, frag-native state) =================
// Distributed barrier, release/acquire atomics, pure spin poll (no nanosleep).
__device__ __forceinline__ void grid_barrier(unsigned target16, int bid) {
    __syncthreads();
    if (threadIdx.x == 0) {
        asm volatile("red.release.gpu.global.add.u32 [%0], 1;"
                     :: "l"(&g_bar8[(bid & 7) * 32]) : "memory");
    }
    if (threadIdx.x < 8) {
        unsigned v;
        do {
            asm volatile("ld.acquire.gpu.global.u32 %0, [%1];"
                         : "=r"(v) : "l"(&g_bar8[threadIdx.x * 32]) : "memory");
        } while (v < target16);
    }
    __syncthreads();
}

// smem: h-frag hi 32KB + h-frag lo 32KB + red/gbuf 8KB = 72KB
#define SMEM_BYTES (72 * 1024)

__global__ __launch_bounds__(512, 1) void lstm_persist(
    const float* __restrict__ xg,       // (B*T, 8192)
    const uint4* __restrict__ whp,      // packed Wh fragments [1024][64][32]
    const uint4* __restrict__ projp,    // packed proj fragments [128][128][32]
    float* __restrict__ c,              // (16, 2048)
    float* __restrict__ h,              // (16, 1024) scalar (for tail)
    float* __restrict__ hs,             // (B*T, 1024)
    int T)
{
    extern __shared__ __align__(16) char dynsmem[];
    uint4* sh_hi = (uint4*)dynsmem;                 // 2048 uint4
    uint4* sh_lo = sh_hi + 2048;                    // 2048 uint4
    float* red   = (float*)(dynsmem + 64 * 1024);   // 1024 floats
    float* gbuf  = red + 1024;                      // 1024 floats

    unsigned* sfh32 = (unsigned*)g_sfh;
    unsigned* sfl32 = (unsigned*)g_sfl;
    unsigned* hfh32 = (unsigned*)g_hfh;
    unsigned* hfl32 = (unsigned*)g_hfl;

    const int tid  = threadIdx.x;
    const int lane = tid & 31;
    const int warp = tid >> 5;        // 0..15
    const int bid  = blockIdx.x;
    const int d0   = bid * 16;
    const int p0   = bid * 8;

    // phase A warp mapping: warps 0..7, each owns one ntile (8 gate-cols) over full K=1024
    const int gateA = warp >> 1;      // valid for warp<8
    const int halfA = warp & 1;
    const int ntA  = gateA * 256 + bid * 2 + halfA;
    const uint4* wpA = whp + ((size_t)(ntA * 64)) * 32 + lane;

    const int lg = lane >> 2;
    const int lt = lane & 3;

    // cell-update mapping (tid < 128)
    const int cb = tid >> 3;
    const int cj = tid & 7;
    const int s_idx = (((bid * 32) + (cb & 7) * 4 + (cj & 3)) << 2) + ((cb >> 3) + 2 * ((cj >> 2) & 1));
    const int hb = tid >> 3;
    const int hp = tid & 7;
    const int h_idx = ((((bid >> 1) * 32) + (hb & 7) * 4 + (hp >> 1)) << 2) + ((hb >> 3) + 2 * (bid & 1));

    unsigned epoch = 0;

    for (int t = 0; t < T; t++) {
        // ---- prefetch xg (4 gates x d-pair) + old c ----
        float2 xgv[4], cold;
        if (tid < 128) {
            const size_t xrow = ((size_t)(cb * T + t)) * G4;
            const int dloc = d0 + 2 * cj;
#pragma unroll
            for (int g = 0; g < 4; g++)
                xgv[g] = *(const float2*)&xg[xrow + g * DD + dloc];
            cold = *(const float2*)&c[cb * DD + dloc];
        }

        // ---- stage h A-fragments global -> smem (all 16 warps) ----
#pragma unroll
        for (int i = 0; i < 4; i++) {
            const int idx = tid + i * 512;
            sh_hi[idx] = __ldcg(&g_hfh[idx]);
            sh_lo[idx] = __ldcg(&g_hfl[idx]);
        }
        __syncthreads();

        // ---- phase A mma: warps 0..7, full K, 4 independent accumulators ----
        if (warp < 8) {
            float a0[4] = {0.f, 0.f, 0.f, 0.f};
            float a1[4] = {0.f, 0.f, 0.f, 0.f};
            float a2[4] = {0.f, 0.f, 0.f, 0.f};
            float a3[4] = {0.f, 0.f, 0.f, 0.f};
            const uint4* aph = sh_hi + lane;
            const uint4* apl = sh_lo + lane;
#pragma unroll 2
            for (int ks = 0; ks < 64; ks += 4) {
                uint4 b0 = wpA[(size_t)(ks + 0) * 32];
                uint4 b1 = wpA[(size_t)(ks + 1) * 32];
                uint4 b2 = wpA[(size_t)(ks + 2) * 32];
                uint4 b3 = wpA[(size_t)(ks + 3) * 32];
                uint4 ah0 = aph[(ks + 0) * 32], al0 = apl[(ks + 0) * 32];
                uint4 ah1 = aph[(ks + 1) * 32], al1 = apl[(ks + 1) * 32];
                uint4 ah2 = aph[(ks + 2) * 32], al2 = apl[(ks + 2) * 32];
                uint4 ah3 = aph[(ks + 3) * 32], al3 = apl[(ks + 3) * 32];
                mma3(a0, ah0, al0, b0);
                mma3(a1, ah1, al1, b1);
                mma3(a2, ah2, al2, b2);
                mma3(a3, ah3, al3, b3);
            }
            // direct gbuf epilogue (no k-half reduce needed)
            const int ddb = halfA * 8 + 2 * lt;
            gbuf[(lg * 16 + ddb) * 4 + gateA]           = (a0[0] + a1[0]) + (a2[0] + a3[0]);
            gbuf[(lg * 16 + ddb + 1) * 4 + gateA]       = (a0[1] + a1[1]) + (a2[1] + a3[1]);
            gbuf[((lg + 8) * 16 + ddb) * 4 + gateA]     = (a0[2] + a1[2]) + (a2[2] + a3[2]);
            gbuf[((lg + 8) * 16 + ddb + 1) * 4 + gateA] = (a0[3] + a1[3]) + (a2[3] + a3[3]);
        }
        __syncthreads();

        // ---- cell update: writes c (scalar) and s (fragment-native) ----
        if (tid < 128) {
            float4 gv0 = *(float4*)&gbuf[(cb * 16 + 2 * cj) * 4];
            float4 gv1 = *(float4*)&gbuf[(cb * 16 + 2 * cj + 1) * 4];
            float si0 = 1.0f / (1.0f + expf(-(gv0.x + xgv[0].x)));
            float sj0 = tanhf(gv0.y + xgv[1].x);
            float sf0 = 1.0f / (1.0f + expf(-(gv0.z + xgv[2].x + 1.0f)));
            float so0 = 1.0f / (1.0f + expf(-(gv0.w + xgv[3].x)));
            float cn0 = sf0 * cold.x + si0 * sj0;
            float s0 = so0 * tanhf(cn0);
            float si1 = 1.0f / (1.0f + expf(-(gv1.x + xgv[0].y)));
            float sj1 = tanhf(gv1.y + xgv[1].y);
            float sf1 = 1.0f / (1.0f + expf(-(gv1.z + xgv[2].y + 1.0f)));
            float so1 = 1.0f / (1.0f + expf(-(gv1.w + xgv[3].y)));
            float cn1 = sf1 * cold.y + si1 * sj1;
            float s1 = so1 * tanhf(cn1);

            *(float2*)&c[cb * DD + d0 + 2 * cj] = make_float2(cn0, cn1);

            unsigned hiw, low;
            bsplit2(s0, s1, hiw, low);
            sfh32[s_idx] = hiw;
            sfl32[s_idx] = low;
        }

        epoch++;
        grid_barrier(epoch * 16, bid);

        // ---- phase B mma: h = s @ proj (2 independent accumulators, frags from L2) ----
        float p0a[4] = {0.f, 0.f, 0.f, 0.f};
        float p1a[4] = {0.f, 0.f, 0.f, 0.f};
        {
            const uint4* pp = projp + ((size_t)(bid * 128 + warp * 8)) * 32 + lane;
            const uint4* aph = g_sfh + (warp * 8) * 32 + lane;
            const uint4* apl = g_sfl + (warp * 8) * 32 + lane;
#pragma unroll
            for (int ks = 0; ks < 8; ks += 2) {
                uint4 b0 = pp[(size_t)(ks + 0) * 32];
                uint4 b1 = pp[(size_t)(ks + 1) * 32];
                uint4 ah0 = __ldcg(&aph[(ks + 0) * 32]);
                uint4 al0 = __ldcg(&apl[(ks + 0) * 32]);
                uint4 ah1 = __ldcg(&aph[(ks + 1) * 32]);
                uint4 al1 = __ldcg(&apl[(ks + 1) * 32]);
                mma3(p0a, ah0, al0, b0);
                mma3(p1a, ah1, al1, b1);
            }
        }
        float accp[4];
#pragma unroll
        for (int r = 0; r < 4; r++) accp[r] = p0a[r] + p1a[r];

#pragma unroll
        for (int r = 0; r < 4; r++) red[(warp * 32 + lane) * 4 + r] = accp[r];
        __syncthreads();

        if (tid < 128) {
            const int b = hb;
            const int p = hp;
            const int rl = (b & 7) * 4 + (p >> 1);
            const int rr = (b < 8) ? (p & 1) : (2 + (p & 1));
            float v = 0.0f;
#pragma unroll
            for (int w = 0; w < 16; w++) v += red[(w * 32 + rl) * 4 + rr];
            h[b * PP + p0 + p] = v;
            hs[((size_t)(b * T + t)) * PP + p0 + p] = v;
            float vp = __shfl_xor_sync(0xffffffffu, v, 1);
            if ((tid & 1) == 0) {
                unsigned hiw, low;
                bsplit2(v, vp, hiw, low);
                hfh32[h_idx] = hiw;
                hfl32[h_idx] = low;
            }
        }

        epoch++;
        grid_barrier(epoch * 16, bid);
    }
}

// ================= LayerNorm over rows of 1024 =================
__global__ __launch_bounds__(256) void ln_kernel(
    const float* __restrict__ x, const float* __restrict__ gam,
    const float* __restrict__ bet, float* __restrict__ y)
{
    __shared__ float sred[256];
    const size_t r = blockIdx.x;
    const float* xr = x + r * PP;
    const int tid = threadIdx.x;

    float v[4];
#pragma unroll
    for (int i = 0; i < 4; i++) v[i] = xr[tid + i * 256];
    float sm = v[0] + v[1] + v[2] + v[3];
    sred[tid] = sm;
    __syncthreads();
    for (int off = 128; off > 0; off >>= 1) {
        if (tid < off) sred[tid] += sred[tid + off];
        __syncthreads();
    }
    float mean = sred[0] * (1.0f / 1024.0f);
    __syncthreads();

    float q = 0.0f;
#pragma unroll
    for (int i = 0; i < 4; i++) { float d = v[i] - mean; q += d * d; }
    sred[tid] = q;
    __syncthreads();
    for (int off = 128; off > 0; off >>= 1) {
        if (tid < off) sred[tid] += sred[tid + off];
        __syncthreads();
    }
    float inv = rsqrtf(sred[0] * (1.0f / 1024.0f) + 1e-3f);

#pragma unroll
    for (int i = 0; i < 4; i++) {
        int col = tid + i * 256;
        y[r * PP + col] = (v[i] - mean) * inv * gam[col] + bet[col];
    }
}

// ================= conv im2col =================
__global__ __launch_bounds__(256) void build_convA(
    const float* __restrict__ ln, float* __restrict__ Acat)
{
    size_t idx = (size_t)blockIdx.x * 256 + threadIdx.x;
    if (idx >= (size_t)BB * TR * DD) return;
    int m = (int)(idx >> 11);
    int k = (int)(idx & 2047);
    int b = m / TR;
    int t = m - b * TR;
    int w = k >> 10;
    int p = k & 1023;
    Acat[idx] = ln[((size_t)(b * T0 + t + w)) * PP + p];
}

// ================= tail =================
__global__ __launch_bounds__(256) void write_tail(
    const float* __restrict__ c, const float* __restrict__ h, float* __restrict__ out)
{
    const size_t base = (size_t)BB * TR * PP;
    int i = blockIdx.x * 256 + threadIdx.x;
    if (i < BB * DD) out[base + i] = c[i];
    if (i < BB * PP) out[base + BB * DD + i] = h[i];
}

// ================= orchestration =================
extern "C" void kernel_launch(void* const* d_in, const int* in_sizes, int n_in,
                              void* d_out, int out_size)
{
    const float* inputs  = (const float*)d_in[0];
    const float* state   = (const float*)d_in[1];
    const float* kernels = (const float*)d_in[2];
    const float* biases  = (const float*)d_in[3];
    const float* projs   = (const float*)d_in[4];
    const float* gamma   = (const float*)d_in[5];
    const float* beta    = (const float*)d_in[6];
    const float* convw   = (const float*)d_in[7];
    const float* convb   = (const float*)d_in[8];
    float* out = (float*)d_out;

    float *xg, *bufA, *bufB, *convA, *hs, *c, *h;
    uint4 *whp, *projp;
    cudaGetSymbolAddress((void**)&xg,    g_xg);
    cudaGetSymbolAddress((void**)&bufA,  g_bufA);
    cudaGetSymbolAddress((void**)&bufB,  g_bufB);
    cudaGetSymbolAddress((void**)&convA, g_convA);
    cudaGetSymbolAddress((void**)&hs,    g_hs);
    cudaGetSymbolAddress((void**)&whp,   g_whp);
    cudaGetSymbolAddress((void**)&projp, g_projp);
    cudaGetSymbolAddress((void**)&c,     g_c);
    cudaGetSymbolAddress((void**)&h,     g_h);

    static int smem_set = 0;
    if (!smem_set) {
        cudaFuncSetAttribute(lstm_persist, cudaFuncAttributeMaxDynamicSharedMemorySize, SMEM_BYTES);
        smem_set = 1;
    }

    // host launch 0
    setup_all<<<128, 256>>>(state);

    const float* x = inputs;
    int T = T0;
    for (int l = 0; l < NL; l++) {
        const float* Wx = kernels + (size_t)l * 2 * PP * G4;
        const float* Wh = Wx + (size_t)PP * G4;
        const float* bi = biases + (size_t)l * G4;
        const float* pr = projs + (size_t)l * DD * PP;
        const int M = BB * T;

        // host launch 1 (layer 0): combined weight packing
        pack_both<<<8192 + 2048, 256>>>(Wh, whp, pr, projp);

        // host launch 2: xg GEMM (also resets barrier counters)
        dim3 g1(G4 / GBN, (M + GBM - 1) / GBM);
        gemm_bf16<<<g1, 256>>>(x, Wx, bi, xg, M, G4, PP);

        // host launch 3: persistent recurrent kernel (ncu capture target)
        lstm_persist<<<NBLK, 512, SMEM_BYTES>>>(xg, whp, projp, c, h, hs, T);

        float* lnout = (l == 0) ? bufA : (l == 1) ? bufB : (l == 2) ? bufA : out;
        ln_kernel<<<BB * T, 256>>>(hs, gamma, beta, lnout);

        if (l == 1) {
            build_convA<<<(BB * TR * DD + 255) / 256, 256>>>(bufB, convA);
            dim3 g2(PP / GBN, (BB * TR + GBM - 1) / GBM);
            gemm_bf16<<<g2, 256>>>(convA, convw, convb, bufA, BB * TR, PP, DD);
            T = TR;
            x = bufA;
        } else {
            x = bufA;
        }
    }

    write_tail<<<128, 256>>>(c, h, out);
}